// round 10
// baseline (speedup 1.0000x reference)
#include <cuda_runtime.h>
#include <cuda_bf16.h>
#include <math.h>

#define N_NODES 50000
#define N_EDGES 800000
#define FEAT    128
#define HID     64
#define TYPE_NUM 10

// ---------------- scratch buffers (float4-typed => 16B alignment) -----------
__device__ float4 g_y [N_NODES * HID / 4];   // transformed features / layer-3 agg
__device__ float4 g_rA[N_NODES * HID / 4];   // root part / h (ping)
__device__ float4 g_rB[N_NODES * HID / 4];   // root part / h (pong)
__device__ unsigned char g_flag[N_NODES];    // layer-2 active-node flags
__device__ int g_deg   [N_NODES];
__device__ int g_rowptr[N_NODES];
__device__ int g_cursor[N_NODES];
__device__ int g_csr   [N_EDGES];            // src node per CSR slot

// packed f32x2 helpers --------------------------------------------------------
#define FMA2(acc, a, b) \
    asm("fma.rn.f32x2 %0, %1, %2, %3;" : "=l"(acc) : "l"(a), "l"(b), "l"(acc))

__device__ __forceinline__ unsigned long long bcast2(float v) {
    unsigned long long r;
    unsigned u = __float_as_uint(v);
    asm("mov.b64 %0, {%1, %1};" : "=l"(r) : "r"(u));
    return r;
}
__device__ __forceinline__ float f2_lo(unsigned long long v) {
    return __uint_as_float((unsigned)v);
}
__device__ __forceinline__ float f2_hi(unsigned long long v) {
    return __uint_as_float((unsigned)(v >> 32));
}

// ---------------------------------------------------------------------------
// CSR build
// ---------------------------------------------------------------------------
__global__ void __launch_bounds__(256) node_init(
    const int* __restrict__ batch, int* __restrict__ deg,
    unsigned char* __restrict__ flag, int N)
{
    int t = blockIdx.x * 256 + threadIdx.x;
    if (t >= N) return;
    deg[t] = 0;
    flag[t] = (batch[t] == 0) ? 1 : 0;
}

// 4 edges per thread (int4 loads) — higher MLP on the latency-bound path
__global__ void __launch_bounds__(256) edge_hist(
    const int4* __restrict__ eis, const int4* __restrict__ eid,
    const int* __restrict__ batch,
    int* __restrict__ deg, unsigned char* __restrict__ flag, int E4)
{
    int t = blockIdx.x * 256 + threadIdx.x;
    if (t >= E4) return;
    int4 s = eis[t];
    int4 d = eid[t];
    atomicAdd(&deg[d.x], 1);
    atomicAdd(&deg[d.y], 1);
    atomicAdd(&deg[d.z], 1);
    atomicAdd(&deg[d.w], 1);
    if (batch[d.x] == 0) flag[s.x] = 1;
    if (batch[d.y] == 0) flag[s.y] = 1;
    if (batch[d.z] == 0) flag[s.z] = 1;
    if (batch[d.w] == 0) flag[s.w] = 1;
}

// Single-block chunked exclusive scan: rowptr/cursor = exclusive prefix of deg
__global__ void __launch_bounds__(1024) scan_rowptr(
    const int* __restrict__ deg, int* __restrict__ rowptr,
    int* __restrict__ cursor, int N)
{
    __shared__ int warpsum[32];
    __shared__ int sBase;
    const int tid  = threadIdx.x;
    const int lane = tid & 31;
    const int wid  = tid >> 5;
    if (tid == 0) sBase = 0;
    __syncthreads();
    const int nchunk = (N + 1023) >> 10;
    for (int c = 0; c < nchunk; c++) {
        int idx = (c << 10) + tid;
        int v = (idx < N) ? deg[idx] : 0;
        int x = v;
        #pragma unroll
        for (int d = 1; d < 32; d <<= 1) {
            int t = __shfl_up_sync(0xffffffff, x, d);
            if (lane >= d) x += t;
        }
        if (lane == 31) warpsum[wid] = x;
        __syncthreads();
        if (wid == 0) {
            int w = warpsum[lane];
            #pragma unroll
            for (int d = 1; d < 32; d <<= 1) {
                int t = __shfl_up_sync(0xffffffff, w, d);
                if (lane >= d) w += t;
            }
            warpsum[lane] = w;
        }
        __syncthreads();
        int incl = x + (wid > 0 ? warpsum[wid - 1] : 0);
        int base = sBase;
        if (idx < N) {
            int excl = base + incl - v;
            rowptr[idx] = excl;
            cursor[idx] = excl;
        }
        __syncthreads();
        if (tid == 1023) sBase = base + incl;
        __syncthreads();
    }
}

__global__ void __launch_bounds__(256) fill_csr(
    const int4* __restrict__ eis, const int4* __restrict__ eid,
    int* __restrict__ cursor, int* __restrict__ csr, int E4)
{
    int t = blockIdx.x * 256 + threadIdx.x;
    if (t >= E4) return;
    int4 s = eis[t];
    int4 d = eid[t];
    int a = atomicAdd(&cursor[d.x], 1);
    int b = atomicAdd(&cursor[d.y], 1);
    int c = atomicAdd(&cursor[d.z], 1);
    int e = atomicAdd(&cursor[d.w], 1);
    csr[a] = s.x;
    csr[b] = s.y;
    csr[c] = s.z;
    csr[e] = s.w;
}

// ---------------------------------------------------------------------------
// Dual GEMM, FMA-bound blocking: each thread computes 4 rows x 4 cols x 2 mats.
// tid&15 -> column quad q (cols q, q+16, q+32, q+48), tid>>4 -> row group.
// Weights stored permuted in smem so each thread's 4 cols = one LDS.128.
// ---------------------------------------------------------------------------
template<int K>
__global__ void __launch_bounds__(256) dual_gemm(
    const float* __restrict__ in,
    const float* __restrict__ Wr,  const float* __restrict__ Wo,
    float* __restrict__ y, float* __restrict__ r, int N)
{
    __shared__ float sIn[32][68];   // [k][row], row stride 272B (16B aligned)
    __shared__ float sWr[32][64];   // permuted: [k][q*4+c] = W[k][q+16c]
    __shared__ float sWo[32][64];

    const int tid  = threadIdx.x;
    const int colq = tid & 15;
    const int rowg = tid >> 4;          // 0..15 -> rows rowg*4 .. rowg*4+3
    const int row0 = blockIdx.x * 64;

    unsigned long long accY[4][2], accR[4][2];   // [c][row-pair]
    #pragma unroll
    for (int c = 0; c < 4; c++) {
        accY[c][0] = 0ull; accY[c][1] = 0ull;
        accR[c][0] = 0ull; accR[c][1] = 0ull;
    }

    for (int kc = 0; kc < K; kc += 32) {
        __syncthreads();
        #pragma unroll
        for (int e = 0; e < 8; e++) {
            int linear = tid + e * 256;
            int rl = linear >> 5;
            int kl = linear & 31;
            int grow = row0 + rl;
            sIn[kl][rl] = (grow < N) ? in[(size_t)grow * K + kc + kl] : 0.f;
        }
        #pragma unroll
        for (int e = 0; e < 8; e++) {
            int linear = tid + e * 256;
            int kk = linear >> 6;
            int cc = linear & 63;
            int pos = (cc & 15) * 4 + (cc >> 4);
            sWr[kk][pos] = Wr[(size_t)(kc + kk) * HID + cc];
            sWo[kk][pos] = Wo[(size_t)(kc + kk) * HID + cc];
        }
        __syncthreads();

        #pragma unroll
        for (int k = 0; k < 32; k++) {
            float4 w4r = *(const float4*)(&sWr[k][colq * 4]);
            float4 w4o = *(const float4*)(&sWo[k][colq * 4]);
            ulonglong2 a = *(const ulonglong2*)(&sIn[k][rowg * 4]);
            unsigned long long wr0 = bcast2(w4r.x), wr1 = bcast2(w4r.y);
            unsigned long long wr2 = bcast2(w4r.z), wr3 = bcast2(w4r.w);
            unsigned long long wo0 = bcast2(w4o.x), wo1 = bcast2(w4o.y);
            unsigned long long wo2 = bcast2(w4o.z), wo3 = bcast2(w4o.w);
            FMA2(accY[0][0], a.x, wr0);  FMA2(accY[0][1], a.y, wr0);
            FMA2(accY[1][0], a.x, wr1);  FMA2(accY[1][1], a.y, wr1);
            FMA2(accY[2][0], a.x, wr2);  FMA2(accY[2][1], a.y, wr2);
            FMA2(accY[3][0], a.x, wr3);  FMA2(accY[3][1], a.y, wr3);
            FMA2(accR[0][0], a.x, wo0);  FMA2(accR[0][1], a.y, wo0);
            FMA2(accR[1][0], a.x, wo1);  FMA2(accR[1][1], a.y, wo1);
            FMA2(accR[2][0], a.x, wo2);  FMA2(accR[2][1], a.y, wo2);
            FMA2(accR[3][0], a.x, wo3);  FMA2(accR[3][1], a.y, wo3);
        }
    }

    const int rb = row0 + rowg * 4;
    #pragma unroll
    for (int c = 0; c < 4; c++) {
        int col = colq + 16 * c;
        #pragma unroll
        for (int p = 0; p < 2; p++) {
            int r0 = rb + p * 2;
            if (r0 < N) {
                y[(size_t)r0 * HID + col] = f2_lo(accY[c][p]);
                r[(size_t)r0 * HID + col] = f2_lo(accR[c][p]);
            }
            if (r0 + 1 < N) {
                y[(size_t)(r0 + 1) * HID + col] = f2_hi(accY[c][p]);
                r[(size_t)(r0 + 1) * HID + col] = f2_hi(accR[c][p]);
            }
        }
    }
}

// ---------------------------------------------------------------------------
// CSR gather aggregation. 16 threads per node, register accumulation.
// MODE 0: all nodes,      out = relu(acc + r)   (in place over r)
// MODE 1: flagged nodes,  out = relu(acc + r)
// MODE 2: graph-0 nodes,  out = acc             (raw agg for layer 3)
// ---------------------------------------------------------------------------
template<int MODE>
__global__ void __launch_bounds__(256) gather_agg(
    const float4* __restrict__ y, const int* __restrict__ rowptr,
    const int* __restrict__ deg, const int* __restrict__ csr,
    const unsigned char* __restrict__ flag, const int* __restrict__ batch,
    float4* r_io, int N)
{
    int t = blockIdx.x * 256 + threadIdx.x;
    int node = t >> 4;
    if (node >= N) return;
    if (MODE == 1 && !flag[node]) return;
    if (MODE == 2 && batch[node] != 0) return;
    int lane = t & 15;
    int start = rowptr[node];
    int end   = start + deg[node];

    float4 acc = make_float4(0.f, 0.f, 0.f, 0.f);
    int e = start;
    for (; e + 4 <= end; e += 4) {
        int s0 = csr[e], s1 = csr[e+1], s2 = csr[e+2], s3 = csr[e+3];
        float4 v0 = y[(size_t)s0 * 16 + lane];
        float4 v1 = y[(size_t)s1 * 16 + lane];
        float4 v2 = y[(size_t)s2 * 16 + lane];
        float4 v3 = y[(size_t)s3 * 16 + lane];
        acc.x += (v0.x + v1.x) + (v2.x + v3.x);
        acc.y += (v0.y + v1.y) + (v2.y + v3.y);
        acc.z += (v0.z + v1.z) + (v2.z + v3.z);
        acc.w += (v0.w + v1.w) + (v2.w + v3.w);
    }
    for (; e < end; e++) {
        float4 v = y[(size_t)csr[e] * 16 + lane];
        acc.x += v.x; acc.y += v.y; acc.z += v.z; acc.w += v.w;
    }

    size_t o = (size_t)node * 16 + lane;
    if (MODE == 2) {
        r_io[o] = acc;
    } else {
        float4 b = r_io[o];
        b.x = fmaxf(acc.x + b.x, 0.f);
        b.y = fmaxf(acc.y + b.y, 0.f);
        b.z = fmaxf(acc.z + b.z, 0.f);
        b.w = fmaxf(acc.w + b.w, 0.f);
        r_io[o] = b;
    }
}

// ---------------------------------------------------------------------------
// Layer-3 GEMM on the graph-0 prefix only: h3 = relu(agg@Wr + h2@Wo)
// ---------------------------------------------------------------------------
__global__ void __launch_bounds__(256) gemm3_prefix(
    const float* __restrict__ agg, const float* __restrict__ h2,
    const float* __restrict__ Wr,  const float* __restrict__ Wo,
    const int* __restrict__ batch, float* __restrict__ h3, int N)
{
    const int row0 = blockIdx.x * 64;
    if (batch[row0] != 0) return;

    __shared__ float sA[32][68];
    __shared__ float sB[32][68];
    __shared__ float sWr[32][64];
    __shared__ float sWo[32][64];

    const int tid = threadIdx.x;
    const int col = tid & 63;
    const int rg  = tid >> 6;

    unsigned long long acc[8];
    #pragma unroll
    for (int j = 0; j < 8; j++) acc[j] = 0ull;

    for (int kc = 0; kc < HID; kc += 32) {
        __syncthreads();
        #pragma unroll
        for (int e = 0; e < 8; e++) {
            int linear = tid + e * 256;
            int rl = linear >> 5;
            int kl = linear & 31;
            int grow = row0 + rl;
            float va = 0.f, vb = 0.f;
            if (grow < N) {
                size_t idx = (size_t)grow * HID + kc + kl;
                va = agg[idx];
                vb = h2[idx];
            }
            sA[kl][rl] = va;
            sB[kl][rl] = vb;
        }
        #pragma unroll
        for (int e = 0; e < 8; e++) {
            int linear = tid + e * 256;
            int kk = linear >> 6;
            int cc = linear & 63;
            sWr[kk][cc] = Wr[(size_t)(kc + kk) * HID + cc];
            sWo[kk][cc] = Wo[(size_t)(kc + kk) * HID + cc];
        }
        __syncthreads();

        #pragma unroll
        for (int k = 0; k < 32; k++) {
            unsigned long long wr2 = bcast2(sWr[k][col]);
            unsigned long long wo2 = bcast2(sWo[k][col]);
            const ulonglong2* ra = (const ulonglong2*)(&sA[k][rg * 16]);
            const ulonglong2* rb = (const ulonglong2*)(&sB[k][rg * 16]);
            #pragma unroll
            for (int q = 0; q < 4; q++) {
                ulonglong2 a = ra[q];
                ulonglong2 b = rb[q];
                FMA2(acc[q*2+0], a.x, wr2);
                FMA2(acc[q*2+1], a.y, wr2);
                FMA2(acc[q*2+0], b.x, wo2);
                FMA2(acc[q*2+1], b.y, wo2);
            }
        }
    }

    #pragma unroll
    for (int j = 0; j < 16; j++) {
        int grow = row0 + rg * 16 + j;
        if (grow < N) {
            float v = (j & 1) ? f2_hi(acc[j >> 1]) : f2_lo(acc[j >> 1]);
            h3[(size_t)grow * HID + col] = fmaxf(v, 0.f);
        }
    }
}

// ---------------------------------------------------------------------------
// Mean-pool graph 0, fc head, softmax
// ---------------------------------------------------------------------------
__global__ void __launch_bounds__(256) pool_head(
    const float* __restrict__ h, const int* __restrict__ batch,
    const float* __restrict__ Wfc, const float* __restrict__ bfc,
    float* __restrict__ out, int N)
{
    __shared__ float ssum[4][HID];
    __shared__ float scnt[4];
    __shared__ float smean[HID];
    __shared__ float slog[TYPE_NUM];

    int tid = threadIdx.x;
    int g = tid >> 6;
    int d = tid & 63;

    float acc = 0.f;
    int cnt = 0;
    for (int i = g; i < N; i += 4) {
        if (batch[i] != 0) break;
        acc += h[(size_t)i * HID + d];
        cnt++;
    }
    ssum[g][d] = acc;
    if (d == 0) scnt[g] = (float)cnt;
    __syncthreads();

    if (tid < HID) {
        float m = ssum[0][tid] + ssum[1][tid] + ssum[2][tid] + ssum[3][tid];
        float c = scnt[0] + scnt[1] + scnt[2] + scnt[3];
        smean[tid] = m / fmaxf(c, 1.f);
    }
    __syncthreads();

    if (tid < TYPE_NUM) {
        float l = bfc[tid];
        #pragma unroll
        for (int k = 0; k < HID; k++) l += smean[k] * Wfc[k * TYPE_NUM + tid];
        slog[tid] = l;
    }
    __syncthreads();

    if (tid == 0) {
        float mx = slog[0];
        #pragma unroll
        for (int j = 1; j < TYPE_NUM; j++) mx = fmaxf(mx, slog[j]);
        float s = 0.f;
        float ex[TYPE_NUM];
        #pragma unroll
        for (int j = 0; j < TYPE_NUM; j++) { ex[j] = __expf(slog[j] - mx); s += ex[j]; }
        float inv = 1.f / s;
        #pragma unroll
        for (int j = 0; j < TYPE_NUM; j++) out[j] = ex[j] * inv;
    }
}

// ---------------------------------------------------------------------------
extern "C" void kernel_launch(void* const* d_in, const int* in_sizes, int n_in,
                              void* d_out, int out_size)
{
    const float* x      = (const float*)d_in[0];
    const int*   ei     = (const int*)  d_in[1];
    const int*   batch  = (const int*)  d_in[2];
    const float* Wrel1  = (const float*)d_in[3];
    const float* Wroot1 = (const float*)d_in[4];
    const float* Wrel2  = (const float*)d_in[5];
    const float* Wroot2 = (const float*)d_in[6];
    const float* Wrel3  = (const float*)d_in[7];
    const float* Wroot3 = (const float*)d_in[8];
    const float* Wfc    = (const float*)d_in[9];
    const float* bfc    = (const float*)d_in[10];
    float* out = (float*)d_out;

    float4 *py4, *prA4, *prB4;
    unsigned char* pflag;
    int *pdeg, *prow, *pcur, *pcsr;
    cudaGetSymbolAddress((void**)&py4,   g_y);
    cudaGetSymbolAddress((void**)&prA4,  g_rA);
    cudaGetSymbolAddress((void**)&prB4,  g_rB);
    cudaGetSymbolAddress((void**)&pflag, g_flag);
    cudaGetSymbolAddress((void**)&pdeg,  g_deg);
    cudaGetSymbolAddress((void**)&prow,  g_rowptr);
    cudaGetSymbolAddress((void**)&pcur,  g_cursor);
    cudaGetSymbolAddress((void**)&pcsr,  g_csr);
    float* py  = (float*)py4;
    float* prA = (float*)prA4;
    float* prB = (float*)prB4;

    const int N = N_NODES, E = N_EDGES;
    const int E4 = E / 4;
    const int nodeB  = (N + 255) / 256;
    const int edge4B = (E4 + 255) / 256;
    const int gemmB  = (N + 63) / 64;
    const int gathB  = (N * 16 + 255) / 256;

    const int4* eis = (const int4*)ei;
    const int4* eid = (const int4*)(ei + E);

    // CSR build + flags
    node_init  <<<nodeB, 256>>>(batch, pdeg, pflag, N);
    edge_hist  <<<edge4B, 256>>>(eis, eid, batch, pdeg, pflag, E4);
    scan_rowptr<<<1, 1024>>>(pdeg, prow, pcur, N);
    fill_csr   <<<edge4B, 256>>>(eis, eid, pcur, pcsr, E4);

    // Layer 1 (K=128): y1 = x@Wrel1, rA = x@Wroot1; h1 = relu(gather(y1)+rA)
    dual_gemm<FEAT><<<gemmB, 256>>>(x, Wrel1, Wroot1, py, prA, N);
    gather_agg<0><<<gathB, 256>>>(py4, prow, pdeg, pcsr, pflag, batch, prA4, N);

    // Layer 2 (K=64): y2 = h1@Wrel2, rB = h1@Wroot2; h2 = relu(gather(y2)+rB) on flagged
    dual_gemm<HID><<<gemmB, 256>>>(prA, Wrel2, Wroot2, py, prB, N);
    gather_agg<1><<<gathB, 256>>>(py4, prow, pdeg, pcsr, pflag, batch, prB4, N);

    // Layer 3 (graph-0 prefix): agg3 = gather(h2) into py, then GEMM
    gather_agg<2><<<gathB, 256>>>(prB4, prow, pdeg, pcsr, pflag, batch, py4, N);
    gemm3_prefix<<<gemmB, 256>>>(py, prB, Wrel3, Wroot3, batch, prA, N);

    // Head
    pool_head<<<1, 256>>>(prA, batch, Wfc, bfc, out, N);
}

// round 11
// speedup vs baseline: 1.0231x; 1.0231x over previous
#include <cuda_runtime.h>
#include <cuda_bf16.h>
#include <math.h>

#define N_NODES 50000
#define N_EDGES 800000
#define FEAT    128
#define HID     64
#define TYPE_NUM 10

// ---------------- scratch buffers (float4-typed => 16B alignment) -----------
__device__ float4 g_y [N_NODES * HID / 4];   // transformed features / layer-3 agg
__device__ float4 g_rA[N_NODES * HID / 4];   // root part / h (ping)
__device__ float4 g_rB[N_NODES * HID / 4];   // root part / h (pong)
__device__ unsigned char g_flag[N_NODES];    // layer-2 active-node flags
__device__ int g_deg   [N_NODES];
__device__ int g_rowptr[N_NODES];
__device__ int g_cursor[N_NODES];
__device__ int g_csr   [N_EDGES];            // src node per CSR slot

// packed f32x2 helpers --------------------------------------------------------
#define FMA2(acc, a, b) \
    asm("fma.rn.f32x2 %0, %1, %2, %3;" : "=l"(acc) : "l"(a), "l"(b), "l"(acc))

__device__ __forceinline__ unsigned long long bcast2(float v) {
    unsigned long long r;
    unsigned u = __float_as_uint(v);
    asm("mov.b64 %0, {%1, %1};" : "=l"(r) : "r"(u));
    return r;
}
__device__ __forceinline__ float f2_lo(unsigned long long v) {
    return __uint_as_float((unsigned)v);
}
__device__ __forceinline__ float f2_hi(unsigned long long v) {
    return __uint_as_float((unsigned)(v >> 32));
}

// ---------------------------------------------------------------------------
// CSR build (scalar 1-edge/thread versions — int4 variant regressed)
// ---------------------------------------------------------------------------
__global__ void __launch_bounds__(256) node_init(
    const int* __restrict__ batch, int* __restrict__ deg,
    unsigned char* __restrict__ flag, int N)
{
    int t = blockIdx.x * 256 + threadIdx.x;
    if (t >= N) return;
    deg[t] = 0;
    flag[t] = (batch[t] == 0) ? 1 : 0;
}

__global__ void __launch_bounds__(256) edge_hist(
    const int* __restrict__ ei, const int* __restrict__ batch,
    int* __restrict__ deg, unsigned char* __restrict__ flag, int E)
{
    int t = blockIdx.x * 256 + threadIdx.x;
    if (t >= E) return;
    int s = ei[t];
    int d = ei[E + t];
    atomicAdd(&deg[d], 1);
    if (batch[d] == 0) flag[s] = 1;
}

// Single-block chunked exclusive scan: rowptr/cursor = exclusive prefix of deg
__global__ void __launch_bounds__(1024) scan_rowptr(
    const int* __restrict__ deg, int* __restrict__ rowptr,
    int* __restrict__ cursor, int N)
{
    __shared__ int warpsum[32];
    __shared__ int sBase;
    const int tid  = threadIdx.x;
    const int lane = tid & 31;
    const int wid  = tid >> 5;
    if (tid == 0) sBase = 0;
    __syncthreads();
    const int nchunk = (N + 1023) >> 10;
    for (int c = 0; c < nchunk; c++) {
        int idx = (c << 10) + tid;
        int v = (idx < N) ? deg[idx] : 0;
        int x = v;
        #pragma unroll
        for (int d = 1; d < 32; d <<= 1) {
            int t = __shfl_up_sync(0xffffffff, x, d);
            if (lane >= d) x += t;
        }
        if (lane == 31) warpsum[wid] = x;
        __syncthreads();
        if (wid == 0) {
            int w = warpsum[lane];
            #pragma unroll
            for (int d = 1; d < 32; d <<= 1) {
                int t = __shfl_up_sync(0xffffffff, w, d);
                if (lane >= d) w += t;
            }
            warpsum[lane] = w;
        }
        __syncthreads();
        int incl = x + (wid > 0 ? warpsum[wid - 1] : 0);
        int base = sBase;
        if (idx < N) {
            int excl = base + incl - v;
            rowptr[idx] = excl;
            cursor[idx] = excl;
        }
        __syncthreads();
        if (tid == 1023) sBase = base + incl;
        __syncthreads();
    }
}

__global__ void __launch_bounds__(256) fill_csr(
    const int* __restrict__ ei, int* __restrict__ cursor,
    int* __restrict__ csr, int E)
{
    int t = blockIdx.x * 256 + threadIdx.x;
    if (t >= E) return;
    int d = ei[E + t];
    int slot = atomicAdd(&cursor[d], 1);
    csr[slot] = ei[t];
}

// ---------------------------------------------------------------------------
// Dual GEMM, 4 rows x 4 cols x 2 mats per thread, packed f32x2 FMA.
// ---------------------------------------------------------------------------
template<int K>
__global__ void __launch_bounds__(256) dual_gemm(
    const float* __restrict__ in,
    const float* __restrict__ Wr,  const float* __restrict__ Wo,
    float* __restrict__ y, float* __restrict__ r, int N)
{
    __shared__ float sIn[32][68];   // [k][row], row stride 272B (16B aligned)
    __shared__ float sWr[32][64];   // permuted: [k][q*4+c] = W[k][q+16c]
    __shared__ float sWo[32][64];

    const int tid  = threadIdx.x;
    const int colq = tid & 15;
    const int rowg = tid >> 4;          // 0..15 -> rows rowg*4 .. rowg*4+3
    const int row0 = blockIdx.x * 64;

    unsigned long long accY[4][2], accR[4][2];   // [c][row-pair]
    #pragma unroll
    for (int c = 0; c < 4; c++) {
        accY[c][0] = 0ull; accY[c][1] = 0ull;
        accR[c][0] = 0ull; accR[c][1] = 0ull;
    }

    for (int kc = 0; kc < K; kc += 32) {
        __syncthreads();
        #pragma unroll
        for (int e = 0; e < 8; e++) {
            int linear = tid + e * 256;
            int rl = linear >> 5;
            int kl = linear & 31;
            int grow = row0 + rl;
            sIn[kl][rl] = (grow < N) ? in[(size_t)grow * K + kc + kl] : 0.f;
        }
        #pragma unroll
        for (int e = 0; e < 8; e++) {
            int linear = tid + e * 256;
            int kk = linear >> 6;
            int cc = linear & 63;
            int pos = (cc & 15) * 4 + (cc >> 4);
            sWr[kk][pos] = Wr[(size_t)(kc + kk) * HID + cc];
            sWo[kk][pos] = Wo[(size_t)(kc + kk) * HID + cc];
        }
        __syncthreads();

        #pragma unroll
        for (int k = 0; k < 32; k++) {
            float4 w4r = *(const float4*)(&sWr[k][colq * 4]);
            float4 w4o = *(const float4*)(&sWo[k][colq * 4]);
            ulonglong2 a = *(const ulonglong2*)(&sIn[k][rowg * 4]);
            unsigned long long wr0 = bcast2(w4r.x), wr1 = bcast2(w4r.y);
            unsigned long long wr2 = bcast2(w4r.z), wr3 = bcast2(w4r.w);
            unsigned long long wo0 = bcast2(w4o.x), wo1 = bcast2(w4o.y);
            unsigned long long wo2 = bcast2(w4o.z), wo3 = bcast2(w4o.w);
            FMA2(accY[0][0], a.x, wr0);  FMA2(accY[0][1], a.y, wr0);
            FMA2(accY[1][0], a.x, wr1);  FMA2(accY[1][1], a.y, wr1);
            FMA2(accY[2][0], a.x, wr2);  FMA2(accY[2][1], a.y, wr2);
            FMA2(accY[3][0], a.x, wr3);  FMA2(accY[3][1], a.y, wr3);
            FMA2(accR[0][0], a.x, wo0);  FMA2(accR[0][1], a.y, wo0);
            FMA2(accR[1][0], a.x, wo1);  FMA2(accR[1][1], a.y, wo1);
            FMA2(accR[2][0], a.x, wo2);  FMA2(accR[2][1], a.y, wo2);
            FMA2(accR[3][0], a.x, wo3);  FMA2(accR[3][1], a.y, wo3);
        }
    }

    const int rb = row0 + rowg * 4;
    #pragma unroll
    for (int c = 0; c < 4; c++) {
        int col = colq + 16 * c;
        #pragma unroll
        for (int p = 0; p < 2; p++) {
            int r0 = rb + p * 2;
            if (r0 < N) {
                y[(size_t)r0 * HID + col] = f2_lo(accY[c][p]);
                r[(size_t)r0 * HID + col] = f2_lo(accR[c][p]);
            }
            if (r0 + 1 < N) {
                y[(size_t)(r0 + 1) * HID + col] = f2_hi(accY[c][p]);
                r[(size_t)(r0 + 1) * HID + col] = f2_hi(accR[c][p]);
            }
        }
    }
}

// ---------------------------------------------------------------------------
// CSR gather aggregation. 16 threads per node, register accumulation.
// MODE 0: all nodes,      out = relu(acc + r)   (in place over r)
// MODE 1: flagged nodes,  out = relu(acc + r)
// MODE 2: graph-0 nodes,  out = acc             (raw agg for layer 3)
// ---------------------------------------------------------------------------
template<int MODE>
__global__ void __launch_bounds__(256) gather_agg(
    const float4* __restrict__ y, const int* __restrict__ rowptr,
    const int* __restrict__ deg, const int* __restrict__ csr,
    const unsigned char* __restrict__ flag, const int* __restrict__ batch,
    float4* r_io, int N)
{
    int t = blockIdx.x * 256 + threadIdx.x;
    int node = t >> 4;
    if (node >= N) return;
    if (MODE == 1 && !flag[node]) return;
    if (MODE == 2 && batch[node] != 0) return;
    int lane = t & 15;
    int start = rowptr[node];
    int end   = start + deg[node];

    float4 acc = make_float4(0.f, 0.f, 0.f, 0.f);
    int e = start;
    for (; e + 4 <= end; e += 4) {
        int s0 = csr[e], s1 = csr[e+1], s2 = csr[e+2], s3 = csr[e+3];
        float4 v0 = y[(size_t)s0 * 16 + lane];
        float4 v1 = y[(size_t)s1 * 16 + lane];
        float4 v2 = y[(size_t)s2 * 16 + lane];
        float4 v3 = y[(size_t)s3 * 16 + lane];
        acc.x += (v0.x + v1.x) + (v2.x + v3.x);
        acc.y += (v0.y + v1.y) + (v2.y + v3.y);
        acc.z += (v0.z + v1.z) + (v2.z + v3.z);
        acc.w += (v0.w + v1.w) + (v2.w + v3.w);
    }
    for (; e < end; e++) {
        float4 v = y[(size_t)csr[e] * 16 + lane];
        acc.x += v.x; acc.y += v.y; acc.z += v.z; acc.w += v.w;
    }

    size_t o = (size_t)node * 16 + lane;
    if (MODE == 2) {
        r_io[o] = acc;
    } else {
        float4 b = r_io[o];
        b.x = fmaxf(acc.x + b.x, 0.f);
        b.y = fmaxf(acc.y + b.y, 0.f);
        b.z = fmaxf(acc.z + b.z, 0.f);
        b.w = fmaxf(acc.w + b.w, 0.f);
        r_io[o] = b;
    }
}

// ---------------------------------------------------------------------------
// Layer-3 GEMM on the graph-0 prefix only: h3 = relu(agg@Wr + h2@Wo)
// ---------------------------------------------------------------------------
__global__ void __launch_bounds__(256) gemm3_prefix(
    const float* __restrict__ agg, const float* __restrict__ h2,
    const float* __restrict__ Wr,  const float* __restrict__ Wo,
    const int* __restrict__ batch, float* __restrict__ h3, int N)
{
    const int row0 = blockIdx.x * 64;
    if (batch[row0] != 0) return;

    __shared__ float sA[32][68];
    __shared__ float sB[32][68];
    __shared__ float sWr[32][64];
    __shared__ float sWo[32][64];

    const int tid = threadIdx.x;
    const int col = tid & 63;
    const int rg  = tid >> 6;

    unsigned long long acc[8];
    #pragma unroll
    for (int j = 0; j < 8; j++) acc[j] = 0ull;

    for (int kc = 0; kc < HID; kc += 32) {
        __syncthreads();
        #pragma unroll
        for (int e = 0; e < 8; e++) {
            int linear = tid + e * 256;
            int rl = linear >> 5;
            int kl = linear & 31;
            int grow = row0 + rl;
            float va = 0.f, vb = 0.f;
            if (grow < N) {
                size_t idx = (size_t)grow * HID + kc + kl;
                va = agg[idx];
                vb = h2[idx];
            }
            sA[kl][rl] = va;
            sB[kl][rl] = vb;
        }
        #pragma unroll
        for (int e = 0; e < 8; e++) {
            int linear = tid + e * 256;
            int kk = linear >> 6;
            int cc = linear & 63;
            sWr[kk][cc] = Wr[(size_t)(kc + kk) * HID + cc];
            sWo[kk][cc] = Wo[(size_t)(kc + kk) * HID + cc];
        }
        __syncthreads();

        #pragma unroll
        for (int k = 0; k < 32; k++) {
            unsigned long long wr2 = bcast2(sWr[k][col]);
            unsigned long long wo2 = bcast2(sWo[k][col]);
            const ulonglong2* ra = (const ulonglong2*)(&sA[k][rg * 16]);
            const ulonglong2* rb = (const ulonglong2*)(&sB[k][rg * 16]);
            #pragma unroll
            for (int q = 0; q < 4; q++) {
                ulonglong2 a = ra[q];
                ulonglong2 b = rb[q];
                FMA2(acc[q*2+0], a.x, wr2);
                FMA2(acc[q*2+1], a.y, wr2);
                FMA2(acc[q*2+0], b.x, wo2);
                FMA2(acc[q*2+1], b.y, wo2);
            }
        }
    }

    #pragma unroll
    for (int j = 0; j < 16; j++) {
        int grow = row0 + rg * 16 + j;
        if (grow < N) {
            float v = (j & 1) ? f2_hi(acc[j >> 1]) : f2_lo(acc[j >> 1]);
            h3[(size_t)grow * HID + col] = fmaxf(v, 0.f);
        }
    }
}

// ---------------------------------------------------------------------------
// Mean-pool graph 0, fc head, softmax
// ---------------------------------------------------------------------------
__global__ void __launch_bounds__(256) pool_head(
    const float* __restrict__ h, const int* __restrict__ batch,
    const float* __restrict__ Wfc, const float* __restrict__ bfc,
    float* __restrict__ out, int N)
{
    __shared__ float ssum[4][HID];
    __shared__ float scnt[4];
    __shared__ float smean[HID];
    __shared__ float slog[TYPE_NUM];

    int tid = threadIdx.x;
    int g = tid >> 6;
    int d = tid & 63;

    float acc = 0.f;
    int cnt = 0;
    for (int i = g; i < N; i += 4) {
        if (batch[i] != 0) break;
        acc += h[(size_t)i * HID + d];
        cnt++;
    }
    ssum[g][d] = acc;
    if (d == 0) scnt[g] = (float)cnt;
    __syncthreads();

    if (tid < HID) {
        float m = ssum[0][tid] + ssum[1][tid] + ssum[2][tid] + ssum[3][tid];
        float c = scnt[0] + scnt[1] + scnt[2] + scnt[3];
        smean[tid] = m / fmaxf(c, 1.f);
    }
    __syncthreads();

    if (tid < TYPE_NUM) {
        float l = bfc[tid];
        #pragma unroll
        for (int k = 0; k < HID; k++) l += smean[k] * Wfc[k * TYPE_NUM + tid];
        slog[tid] = l;
    }
    __syncthreads();

    if (tid == 0) {
        float mx = slog[0];
        #pragma unroll
        for (int j = 1; j < TYPE_NUM; j++) mx = fmaxf(mx, slog[j]);
        float s = 0.f;
        float ex[TYPE_NUM];
        #pragma unroll
        for (int j = 0; j < TYPE_NUM; j++) { ex[j] = __expf(slog[j] - mx); s += ex[j]; }
        float inv = 1.f / s;
        #pragma unroll
        for (int j = 0; j < TYPE_NUM; j++) out[j] = ex[j] * inv;
    }
}

// ---------------------------------------------------------------------------
extern "C" void kernel_launch(void* const* d_in, const int* in_sizes, int n_in,
                              void* d_out, int out_size)
{
    const float* x      = (const float*)d_in[0];
    const int*   ei     = (const int*)  d_in[1];
    const int*   batch  = (const int*)  d_in[2];
    const float* Wrel1  = (const float*)d_in[3];
    const float* Wroot1 = (const float*)d_in[4];
    const float* Wrel2  = (const float*)d_in[5];
    const float* Wroot2 = (const float*)d_in[6];
    const float* Wrel3  = (const float*)d_in[7];
    const float* Wroot3 = (const float*)d_in[8];
    const float* Wfc    = (const float*)d_in[9];
    const float* bfc    = (const float*)d_in[10];
    float* out = (float*)d_out;

    float4 *py4, *prA4, *prB4;
    unsigned char* pflag;
    int *pdeg, *prow, *pcur, *pcsr;
    cudaGetSymbolAddress((void**)&py4,   g_y);
    cudaGetSymbolAddress((void**)&prA4,  g_rA);
    cudaGetSymbolAddress((void**)&prB4,  g_rB);
    cudaGetSymbolAddress((void**)&pflag, g_flag);
    cudaGetSymbolAddress((void**)&pdeg,  g_deg);
    cudaGetSymbolAddress((void**)&prow,  g_rowptr);
    cudaGetSymbolAddress((void**)&pcur,  g_cursor);
    cudaGetSymbolAddress((void**)&pcsr,  g_csr);
    float* py  = (float*)py4;
    float* prA = (float*)prA4;
    float* prB = (float*)prB4;

    // Side stream + events for the CSR-build fork (created once, on the
    // un-captured correctness call; capture sees only record/wait nodes).
    static cudaStream_t sSide = nullptr;
    static cudaEvent_t  evFork = nullptr, evJoin = nullptr;
    if (sSide == nullptr) {
        cudaStreamCreateWithFlags(&sSide, cudaStreamNonBlocking);
        cudaEventCreateWithFlags(&evFork, cudaEventDisableTiming);
        cudaEventCreateWithFlags(&evJoin, cudaEventDisableTiming);
    }

    const int N = N_NODES, E = N_EDGES;
    const int nodeB = (N + 255) / 256;
    const int edgeB = (E + 255) / 256;
    const int gemmB = (N + 63) / 64;
    const int gathB = (N * 16 + 255) / 256;

    // ---- fork: CSR build on side stream, concurrent with gemm1 ----
    cudaEventRecord(evFork, 0);
    cudaStreamWaitEvent(sSide, evFork, 0);
    node_init  <<<nodeB, 256, 0, sSide>>>(batch, pdeg, pflag, N);
    edge_hist  <<<edgeB, 256, 0, sSide>>>(ei, batch, pdeg, pflag, E);
    scan_rowptr<<<1, 1024, 0, sSide>>>(pdeg, prow, pcur, N);
    fill_csr   <<<edgeB, 256, 0, sSide>>>(ei, pcur, pcsr, E);
    cudaEventRecord(evJoin, sSide);

    // gemm1 on the main stream overlaps the whole CSR chain
    dual_gemm<FEAT><<<gemmB, 256>>>(x, Wrel1, Wroot1, py, prA, N);

    // ---- join ----
    cudaStreamWaitEvent(0, evJoin, 0);

    // Layer 1 aggregate: h1 = relu(gather(y1) + rA)
    gather_agg<0><<<gathB, 256>>>(py4, prow, pdeg, pcsr, pflag, batch, prA4, N);

    // Layer 2: y2 = h1@Wrel2, rB = h1@Wroot2; h2 = relu(gather(y2)+rB) on flagged
    dual_gemm<HID><<<gemmB, 256>>>(prA, Wrel2, Wroot2, py, prB, N);
    gather_agg<1><<<gathB, 256>>>(py4, prow, pdeg, pcsr, pflag, batch, prB4, N);

    // Layer 3 (graph-0 prefix): agg3 = gather(h2) into py, then GEMM
    gather_agg<2><<<gathB, 256>>>(prB4, prow, pdeg, pcsr, pflag, batch, py4, N);
    gemm3_prefix<<<gemmB, 256>>>(py, prB, Wrel3, Wroot3, batch, prA, N);

    // Head
    pool_head<<<1, 256>>>(prA, batch, Wfc, bfc, out, N);
}

// round 12
// speedup vs baseline: 1.1169x; 1.0917x over previous
#include <cuda_runtime.h>
#include <cuda_bf16.h>
#include <math.h>

#define N_NODES 50000
#define N_EDGES 800000
#define FEAT    128
#define HID     64
#define TYPE_NUM 10

// ---------------- scratch buffers (float4-typed => 16B alignment) -----------
__device__ float4 g_y [N_NODES * HID / 4];   // transformed features
__device__ float4 g_rA[N_NODES * HID / 4];   // root part / h (ping)
__device__ float4 g_rB[N_NODES * HID / 4];   // root part / h (pong)
__device__ unsigned char g_flag[N_NODES];    // layer-2 active-node flags
__device__ int g_deg   [N_NODES];
__device__ int g_rowptr[N_NODES];
__device__ int g_cursor[N_NODES];
__device__ int g_csr   [N_EDGES];            // src node per CSR slot

// packed f32x2 helpers --------------------------------------------------------
#define FMA2(acc, a, b) \
    asm("fma.rn.f32x2 %0, %1, %2, %3;" : "=l"(acc) : "l"(a), "l"(b), "l"(acc))

__device__ __forceinline__ unsigned long long bcast2(float v) {
    unsigned long long r;
    unsigned u = __float_as_uint(v);
    asm("mov.b64 %0, {%1, %1};" : "=l"(r) : "r"(u));
    return r;
}
__device__ __forceinline__ float f2_lo(unsigned long long v) {
    return __uint_as_float((unsigned)v);
}
__device__ __forceinline__ float f2_hi(unsigned long long v) {
    return __uint_as_float((unsigned)(v >> 32));
}

// ---------------------------------------------------------------------------
// CSR build
// ---------------------------------------------------------------------------
__global__ void __launch_bounds__(256) node_init(
    const int* __restrict__ batch, int* __restrict__ deg,
    unsigned char* __restrict__ flag, int N)
{
    int t = blockIdx.x * 256 + threadIdx.x;
    if (t >= N) return;
    deg[t] = 0;
    flag[t] = (batch[t] == 0) ? 1 : 0;
}

__global__ void __launch_bounds__(256) edge_hist(
    const int* __restrict__ ei, const int* __restrict__ batch,
    int* __restrict__ deg, unsigned char* __restrict__ flag, int E)
{
    int t = blockIdx.x * 256 + threadIdx.x;
    if (t >= E) return;
    int s = ei[t];
    int d = ei[E + t];
    atomicAdd(&deg[d], 1);
    if (batch[d] == 0) flag[s] = 1;
}

// Single-block exclusive scan, 4 elems/thread (int4): 13 chunks for N=50000.
__global__ void __launch_bounds__(1024) scan_rowptr(
    const int4* __restrict__ deg4, int4* __restrict__ rowptr4,
    int4* __restrict__ cursor4, int N4)
{
    __shared__ int warpsum[32];
    __shared__ int sBase;
    const int tid  = threadIdx.x;
    const int lane = tid & 31;
    const int wid  = tid >> 5;
    if (tid == 0) sBase = 0;
    __syncthreads();
    const int nchunk = (N4 + 1023) >> 10;
    for (int c = 0; c < nchunk; c++) {
        int idx = (c << 10) + tid;
        int4 v = (idx < N4) ? deg4[idx] : make_int4(0, 0, 0, 0);
        int s = v.x + v.y + v.z + v.w;
        int x = s;
        #pragma unroll
        for (int d = 1; d < 32; d <<= 1) {
            int t = __shfl_up_sync(0xffffffff, x, d);
            if (lane >= d) x += t;
        }
        if (lane == 31) warpsum[wid] = x;
        __syncthreads();
        if (wid == 0) {
            int w = warpsum[lane];
            #pragma unroll
            for (int d = 1; d < 32; d <<= 1) {
                int t = __shfl_up_sync(0xffffffff, w, d);
                if (lane >= d) w += t;
            }
            warpsum[lane] = w;
        }
        __syncthreads();
        int incl = x + (wid > 0 ? warpsum[wid - 1] : 0);
        int base = sBase;
        if (idx < N4) {
            int e0 = base + incl - s;
            int4 o;
            o.x = e0;
            o.y = e0 + v.x;
            o.z = o.y + v.y;
            o.w = o.z + v.z;
            rowptr4[idx] = o;
            cursor4[idx] = o;
        }
        __syncthreads();
        if (tid == 1023) sBase = base + incl;
        __syncthreads();
    }
}

__global__ void __launch_bounds__(256) fill_csr(
    const int* __restrict__ ei, int* __restrict__ cursor,
    int* __restrict__ csr, int E)
{
    int t = blockIdx.x * 256 + threadIdx.x;
    if (t >= E) return;
    int d = ei[E + t];
    int slot = atomicAdd(&cursor[d], 1);
    csr[slot] = ei[t];
}

// ---------------------------------------------------------------------------
// Dual GEMM, 4 rows x 4 cols x 2 mats per thread, packed f32x2 FMA.
// ---------------------------------------------------------------------------
template<int K>
__global__ void __launch_bounds__(256) dual_gemm(
    const float* __restrict__ in,
    const float* __restrict__ Wr,  const float* __restrict__ Wo,
    float* __restrict__ y, float* __restrict__ r, int N)
{
    __shared__ float sIn[32][68];   // [k][row], row stride 272B (16B aligned)
    __shared__ float sWr[32][64];   // permuted: [k][q*4+c] = W[k][q+16c]
    __shared__ float sWo[32][64];

    const int tid  = threadIdx.x;
    const int colq = tid & 15;
    const int rowg = tid >> 4;          // 0..15 -> rows rowg*4 .. rowg*4+3
    const int row0 = blockIdx.x * 64;

    unsigned long long accY[4][2], accR[4][2];   // [c][row-pair]
    #pragma unroll
    for (int c = 0; c < 4; c++) {
        accY[c][0] = 0ull; accY[c][1] = 0ull;
        accR[c][0] = 0ull; accR[c][1] = 0ull;
    }

    for (int kc = 0; kc < K; kc += 32) {
        __syncthreads();
        #pragma unroll
        for (int e = 0; e < 8; e++) {
            int linear = tid + e * 256;
            int rl = linear >> 5;
            int kl = linear & 31;
            int grow = row0 + rl;
            sIn[kl][rl] = (grow < N) ? in[(size_t)grow * K + kc + kl] : 0.f;
        }
        #pragma unroll
        for (int e = 0; e < 8; e++) {
            int linear = tid + e * 256;
            int kk = linear >> 6;
            int cc = linear & 63;
            int pos = (cc & 15) * 4 + (cc >> 4);
            sWr[kk][pos] = Wr[(size_t)(kc + kk) * HID + cc];
            sWo[kk][pos] = Wo[(size_t)(kc + kk) * HID + cc];
        }
        __syncthreads();

        #pragma unroll
        for (int k = 0; k < 32; k++) {
            float4 w4r = *(const float4*)(&sWr[k][colq * 4]);
            float4 w4o = *(const float4*)(&sWo[k][colq * 4]);
            ulonglong2 a = *(const ulonglong2*)(&sIn[k][rowg * 4]);
            unsigned long long wr0 = bcast2(w4r.x), wr1 = bcast2(w4r.y);
            unsigned long long wr2 = bcast2(w4r.z), wr3 = bcast2(w4r.w);
            unsigned long long wo0 = bcast2(w4o.x), wo1 = bcast2(w4o.y);
            unsigned long long wo2 = bcast2(w4o.z), wo3 = bcast2(w4o.w);
            FMA2(accY[0][0], a.x, wr0);  FMA2(accY[0][1], a.y, wr0);
            FMA2(accY[1][0], a.x, wr1);  FMA2(accY[1][1], a.y, wr1);
            FMA2(accY[2][0], a.x, wr2);  FMA2(accY[2][1], a.y, wr2);
            FMA2(accY[3][0], a.x, wr3);  FMA2(accY[3][1], a.y, wr3);
            FMA2(accR[0][0], a.x, wo0);  FMA2(accR[0][1], a.y, wo0);
            FMA2(accR[1][0], a.x, wo1);  FMA2(accR[1][1], a.y, wo1);
            FMA2(accR[2][0], a.x, wo2);  FMA2(accR[2][1], a.y, wo2);
            FMA2(accR[3][0], a.x, wo3);  FMA2(accR[3][1], a.y, wo3);
        }
    }

    const int rb = row0 + rowg * 4;
    #pragma unroll
    for (int c = 0; c < 4; c++) {
        int col = colq + 16 * c;
        #pragma unroll
        for (int p = 0; p < 2; p++) {
            int r0 = rb + p * 2;
            if (r0 < N) {
                y[(size_t)r0 * HID + col] = f2_lo(accY[c][p]);
                r[(size_t)r0 * HID + col] = f2_lo(accR[c][p]);
            }
            if (r0 + 1 < N) {
                y[(size_t)(r0 + 1) * HID + col] = f2_hi(accY[c][p]);
                r[(size_t)(r0 + 1) * HID + col] = f2_hi(accR[c][p]);
            }
        }
    }
}

// ---------------------------------------------------------------------------
// CSR gather aggregation. 16 threads per node, register accumulation.
// MODE 0: all nodes,      out = relu(acc + r)   (in place over r)
// MODE 1: flagged nodes,  out = relu(acc + r)
// ---------------------------------------------------------------------------
template<int MODE>
__global__ void __launch_bounds__(256) gather_agg(
    const float4* __restrict__ y, const int* __restrict__ rowptr,
    const int* __restrict__ deg, const int* __restrict__ csr,
    const unsigned char* __restrict__ flag,
    float4* r_io, int N)
{
    int t = blockIdx.x * 256 + threadIdx.x;
    int node = t >> 4;
    if (node >= N) return;
    if (MODE == 1 && !flag[node]) return;
    int lane = t & 15;
    int start = rowptr[node];
    int end   = start + deg[node];

    float4 acc = make_float4(0.f, 0.f, 0.f, 0.f);
    int e = start;
    for (; e + 4 <= end; e += 4) {
        int s0 = csr[e], s1 = csr[e+1], s2 = csr[e+2], s3 = csr[e+3];
        float4 v0 = y[(size_t)s0 * 16 + lane];
        float4 v1 = y[(size_t)s1 * 16 + lane];
        float4 v2 = y[(size_t)s2 * 16 + lane];
        float4 v3 = y[(size_t)s3 * 16 + lane];
        acc.x += (v0.x + v1.x) + (v2.x + v3.x);
        acc.y += (v0.y + v1.y) + (v2.y + v3.y);
        acc.z += (v0.z + v1.z) + (v2.z + v3.z);
        acc.w += (v0.w + v1.w) + (v2.w + v3.w);
    }
    for (; e < end; e++) {
        float4 v = y[(size_t)csr[e] * 16 + lane];
        acc.x += v.x; acc.y += v.y; acc.z += v.z; acc.w += v.w;
    }

    size_t o = (size_t)node * 16 + lane;
    float4 b = r_io[o];
    b.x = fmaxf(acc.x + b.x, 0.f);
    b.y = fmaxf(acc.y + b.y, 0.f);
    b.z = fmaxf(acc.z + b.z, 0.f);
    b.w = fmaxf(acc.w + b.w, 0.f);
    r_io[o] = b;
}

// ---------------------------------------------------------------------------
// Layer 3 fused: graph-0 prefix tiles gather agg3 = sum h2[src] straight into
// smem, then h3 = relu(agg3@Wr + h2@Wo). Non-prefix tiles exit immediately.
// ---------------------------------------------------------------------------
__global__ void __launch_bounds__(256) gemm3_fused(
    const float4* __restrict__ h2_4, const float* __restrict__ h2,
    const float* __restrict__ Wr,  const float* __restrict__ Wo,
    const int* __restrict__ rowptr, const int* __restrict__ deg,
    const int* __restrict__ csr, const int* __restrict__ batch,
    float* __restrict__ h3, int N)
{
    const int row0 = blockIdx.x * 64;
    if (batch[row0] != 0) return;

    __shared__ float sA[64][68];    // gathered agg, [k][row], all K=64
    __shared__ float sB[32][68];    // h2 tile, [k][row]
    __shared__ float sWr[32][64];   // permuted
    __shared__ float sWo[32][64];   // permuted

    const int tid  = threadIdx.x;
    const int colq = tid & 15;
    const int rowg = tid >> 4;

    // ---- gather phase: 16 threads per node, 16 nodes per pass, 4 passes ----
    {
        int lane = tid & 15;
        int ng   = tid >> 4;
        #pragma unroll
        for (int pass = 0; pass < 4; pass++) {
            int row  = pass * 16 + ng;
            int grow = row0 + row;
            float4 acc = make_float4(0.f, 0.f, 0.f, 0.f);
            if (grow < N) {
                int start = rowptr[grow];
                int end   = start + deg[grow];
                for (int e = start; e < end; e++) {
                    float4 v = h2_4[(size_t)csr[e] * 16 + lane];
                    acc.x += v.x; acc.y += v.y; acc.z += v.z; acc.w += v.w;
                }
            }
            sA[lane * 4 + 0][row] = acc.x;
            sA[lane * 4 + 1][row] = acc.y;
            sA[lane * 4 + 2][row] = acc.z;
            sA[lane * 4 + 3][row] = acc.w;
        }
    }

    unsigned long long acc[4][2];
    #pragma unroll
    for (int c = 0; c < 4; c++) { acc[c][0] = 0ull; acc[c][1] = 0ull; }

    for (int kc = 0; kc < HID; kc += 32) {
        __syncthreads();
        #pragma unroll
        for (int e = 0; e < 8; e++) {
            int linear = tid + e * 256;
            int rl = linear >> 5;
            int kl = linear & 31;
            int grow = row0 + rl;
            sB[kl][rl] = (grow < N) ? h2[(size_t)grow * HID + kc + kl] : 0.f;
        }
        #pragma unroll
        for (int e = 0; e < 8; e++) {
            int linear = tid + e * 256;
            int kk = linear >> 6;
            int cc = linear & 63;
            int pos = (cc & 15) * 4 + (cc >> 4);
            sWr[kk][pos] = Wr[(size_t)(kc + kk) * HID + cc];
            sWo[kk][pos] = Wo[(size_t)(kc + kk) * HID + cc];
        }
        __syncthreads();

        #pragma unroll
        for (int k = 0; k < 32; k++) {
            float4 w4r = *(const float4*)(&sWr[k][colq * 4]);
            float4 w4o = *(const float4*)(&sWo[k][colq * 4]);
            ulonglong2 a = *(const ulonglong2*)(&sA[kc + k][rowg * 4]);
            ulonglong2 b = *(const ulonglong2*)(&sB[k][rowg * 4]);
            unsigned long long wr0 = bcast2(w4r.x), wr1 = bcast2(w4r.y);
            unsigned long long wr2 = bcast2(w4r.z), wr3 = bcast2(w4r.w);
            unsigned long long wo0 = bcast2(w4o.x), wo1 = bcast2(w4o.y);
            unsigned long long wo2 = bcast2(w4o.z), wo3 = bcast2(w4o.w);
            FMA2(acc[0][0], a.x, wr0);  FMA2(acc[0][1], a.y, wr0);
            FMA2(acc[1][0], a.x, wr1);  FMA2(acc[1][1], a.y, wr1);
            FMA2(acc[2][0], a.x, wr2);  FMA2(acc[2][1], a.y, wr2);
            FMA2(acc[3][0], a.x, wr3);  FMA2(acc[3][1], a.y, wr3);
            FMA2(acc[0][0], b.x, wo0);  FMA2(acc[0][1], b.y, wo0);
            FMA2(acc[1][0], b.x, wo1);  FMA2(acc[1][1], b.y, wo1);
            FMA2(acc[2][0], b.x, wo2);  FMA2(acc[2][1], b.y, wo2);
            FMA2(acc[3][0], b.x, wo3);  FMA2(acc[3][1], b.y, wo3);
        }
    }

    const int rb = row0 + rowg * 4;
    #pragma unroll
    for (int c = 0; c < 4; c++) {
        int col = colq + 16 * c;
        #pragma unroll
        for (int p = 0; p < 2; p++) {
            int r0 = rb + p * 2;
            if (r0 < N)
                h3[(size_t)r0 * HID + col] = fmaxf(f2_lo(acc[c][p]), 0.f);
            if (r0 + 1 < N)
                h3[(size_t)(r0 + 1) * HID + col] = fmaxf(f2_hi(acc[c][p]), 0.f);
        }
    }
}

// ---------------------------------------------------------------------------
// Mean-pool graph 0, fc head, softmax
// ---------------------------------------------------------------------------
__global__ void __launch_bounds__(256) pool_head(
    const float* __restrict__ h, const int* __restrict__ batch,
    const float* __restrict__ Wfc, const float* __restrict__ bfc,
    float* __restrict__ out, int N)
{
    __shared__ float ssum[4][HID];
    __shared__ float scnt[4];
    __shared__ float smean[HID];
    __shared__ float slog[TYPE_NUM];

    int tid = threadIdx.x;
    int g = tid >> 6;
    int d = tid & 63;

    float acc = 0.f;
    int cnt = 0;
    for (int i = g; i < N; i += 4) {
        if (batch[i] != 0) break;
        acc += h[(size_t)i * HID + d];
        cnt++;
    }
    ssum[g][d] = acc;
    if (d == 0) scnt[g] = (float)cnt;
    __syncthreads();

    if (tid < HID) {
        float m = ssum[0][tid] + ssum[1][tid] + ssum[2][tid] + ssum[3][tid];
        float c = scnt[0] + scnt[1] + scnt[2] + scnt[3];
        smean[tid] = m / fmaxf(c, 1.f);
    }
    __syncthreads();

    if (tid < TYPE_NUM) {
        float l = bfc[tid];
        #pragma unroll
        for (int k = 0; k < HID; k++) l += smean[k] * Wfc[k * TYPE_NUM + tid];
        slog[tid] = l;
    }
    __syncthreads();

    if (tid == 0) {
        float mx = slog[0];
        #pragma unroll
        for (int j = 1; j < TYPE_NUM; j++) mx = fmaxf(mx, slog[j]);
        float s = 0.f;
        float ex[TYPE_NUM];
        #pragma unroll
        for (int j = 0; j < TYPE_NUM; j++) { ex[j] = __expf(slog[j] - mx); s += ex[j]; }
        float inv = 1.f / s;
        #pragma unroll
        for (int j = 0; j < TYPE_NUM; j++) out[j] = ex[j] * inv;
    }
}

// ---------------------------------------------------------------------------
extern "C" void kernel_launch(void* const* d_in, const int* in_sizes, int n_in,
                              void* d_out, int out_size)
{
    const float* x      = (const float*)d_in[0];
    const int*   ei     = (const int*)  d_in[1];
    const int*   batch  = (const int*)  d_in[2];
    const float* Wrel1  = (const float*)d_in[3];
    const float* Wroot1 = (const float*)d_in[4];
    const float* Wrel2  = (const float*)d_in[5];
    const float* Wroot2 = (const float*)d_in[6];
    const float* Wrel3  = (const float*)d_in[7];
    const float* Wroot3 = (const float*)d_in[8];
    const float* Wfc    = (const float*)d_in[9];
    const float* bfc    = (const float*)d_in[10];
    float* out = (float*)d_out;

    float4 *py4, *prA4, *prB4;
    unsigned char* pflag;
    int *pdeg, *prow, *pcur, *pcsr;
    cudaGetSymbolAddress((void**)&py4,   g_y);
    cudaGetSymbolAddress((void**)&prA4,  g_rA);
    cudaGetSymbolAddress((void**)&prB4,  g_rB);
    cudaGetSymbolAddress((void**)&pflag, g_flag);
    cudaGetSymbolAddress((void**)&pdeg,  g_deg);
    cudaGetSymbolAddress((void**)&prow,  g_rowptr);
    cudaGetSymbolAddress((void**)&pcur,  g_cursor);
    cudaGetSymbolAddress((void**)&pcsr,  g_csr);
    float* py  = (float*)py4;
    float* prA = (float*)prA4;
    float* prB = (float*)prB4;

    static cudaStream_t sSide = nullptr;
    static cudaEvent_t  evFork = nullptr, evJoin = nullptr;
    if (sSide == nullptr) {
        cudaStreamCreateWithFlags(&sSide, cudaStreamNonBlocking);
        cudaEventCreateWithFlags(&evFork, cudaEventDisableTiming);
        cudaEventCreateWithFlags(&evJoin, cudaEventDisableTiming);
    }

    const int N = N_NODES, E = N_EDGES;
    const int N4 = N / 4;
    const int nodeB = (N + 255) / 256;
    const int edgeB = (E + 255) / 256;
    const int gemmB = (N + 63) / 64;
    const int gathB = (N * 16 + 255) / 256;

    // ---- fork: CSR build on side stream, concurrent with gemm1 ----
    // Submission order places dual_gemm<FEAT> at launch slot #4 for ncu.
    cudaEventRecord(evFork, 0);
    cudaStreamWaitEvent(sSide, evFork, 0);
    node_init  <<<nodeB, 256, 0, sSide>>>(batch, pdeg, pflag, N);          // 1
    edge_hist  <<<edgeB, 256, 0, sSide>>>(ei, batch, pdeg, pflag, E);      // 2
    scan_rowptr<<<1, 1024, 0, sSide>>>((const int4*)pdeg, (int4*)prow,
                                       (int4*)pcur, N4);                   // 3
    dual_gemm<FEAT><<<gemmB, 256>>>(x, Wrel1, Wroot1, py, prA, N);         // 4 (profiled)
    fill_csr   <<<edgeB, 256, 0, sSide>>>(ei, pcur, pcsr, E);              // 5
    cudaEventRecord(evJoin, sSide);
    cudaStreamWaitEvent(0, evJoin, 0);

    // Layer 1 aggregate: h1 = relu(gather(y1) + rA)
    gather_agg<0><<<gathB, 256>>>(py4, prow, pdeg, pcsr, pflag, prA4, N);  // 6

    // Layer 2: y2 = h1@Wrel2, rB = h1@Wroot2; h2 = relu(gather(y2)+rB) on flagged
    dual_gemm<HID><<<gemmB, 256>>>(prA, Wrel2, Wroot2, py, prB, N);        // 7
    gather_agg<1><<<gathB, 256>>>(py4, prow, pdeg, pcsr, pflag, prB4, N);  // 8

    // Layer 3 fused gather+GEMM on graph-0 prefix
    gemm3_fused<<<gemmB, 256>>>(prB4, prB, Wrel3, Wroot3,
                                prow, pdeg, pcsr, batch, prA, N);          // 9

    // Head
    pool_head<<<1, 256>>>(prA, batch, Wfc, bfc, out, N);                   // 10
}

// round 13
// speedup vs baseline: 1.1717x; 1.0491x over previous
#include <cuda_runtime.h>
#include <cuda_bf16.h>
#include <math.h>

#define N_NODES 50000
#define N_EDGES 800000
#define FEAT    128
#define HID     64
#define TYPE_NUM 10

// ---------------- scratch buffers (float4-typed => 16B alignment) -----------
__device__ float4 g_y [N_NODES * HID / 4];   // transformed features
__device__ float4 g_rA[N_NODES * HID / 4];   // root part / h (ping)
__device__ float4 g_rB[N_NODES * HID / 4];   // root part / h (pong)
__device__ unsigned char g_flag[N_NODES];    // layer-2 active-node flags
__device__ int g_deg   [N_NODES];
__device__ int g_rowptr[N_NODES];
__device__ int g_cursor[N_NODES];
__device__ int g_csr   [N_EDGES];            // src node per CSR slot

// packed f32x2 helpers --------------------------------------------------------
#define FMA2(acc, a, b) \
    asm("fma.rn.f32x2 %0, %1, %2, %3;" : "=l"(acc) : "l"(a), "l"(b), "l"(acc))

__device__ __forceinline__ unsigned long long bcast2(float v) {
    unsigned long long r;
    unsigned u = __float_as_uint(v);
    asm("mov.b64 %0, {%1, %1};" : "=l"(r) : "r"(u));
    return r;
}
__device__ __forceinline__ float f2_lo(unsigned long long v) {
    return __uint_as_float((unsigned)v);
}
__device__ __forceinline__ float f2_hi(unsigned long long v) {
    return __uint_as_float((unsigned)(v >> 32));
}

// ---------------------------------------------------------------------------
// CSR build
// ---------------------------------------------------------------------------
__global__ void __launch_bounds__(256) node_init(
    const int* __restrict__ batch, int* __restrict__ deg,
    unsigned char* __restrict__ flag, int N)
{
    int t = blockIdx.x * 256 + threadIdx.x;
    if (t >= N) return;
    deg[t] = 0;
    flag[t] = (batch[t] == 0) ? 1 : 0;
}

__global__ void __launch_bounds__(256) edge_hist(
    const int* __restrict__ ei, const int* __restrict__ batch,
    int* __restrict__ deg, unsigned char* __restrict__ flag, int E)
{
    int t = blockIdx.x * 256 + threadIdx.x;
    if (t >= E) return;
    int s = ei[t];
    int d = ei[E + t];
    atomicAdd(&deg[d], 1);
    if (batch[d] == 0) flag[s] = 1;
}

// Single-block exclusive scan, 4 elems/thread (int4): 13 chunks for N=50000.
__global__ void __launch_bounds__(1024) scan_rowptr(
    const int4* __restrict__ deg4, int4* __restrict__ rowptr4,
    int4* __restrict__ cursor4, int N4)
{
    __shared__ int warpsum[32];
    __shared__ int sBase;
    const int tid  = threadIdx.x;
    const int lane = tid & 31;
    const int wid  = tid >> 5;
    if (tid == 0) sBase = 0;
    __syncthreads();
    const int nchunk = (N4 + 1023) >> 10;
    for (int c = 0; c < nchunk; c++) {
        int idx = (c << 10) + tid;
        int4 v = (idx < N4) ? deg4[idx] : make_int4(0, 0, 0, 0);
        int s = v.x + v.y + v.z + v.w;
        int x = s;
        #pragma unroll
        for (int d = 1; d < 32; d <<= 1) {
            int t = __shfl_up_sync(0xffffffff, x, d);
            if (lane >= d) x += t;
        }
        if (lane == 31) warpsum[wid] = x;
        __syncthreads();
        if (wid == 0) {
            int w = warpsum[lane];
            #pragma unroll
            for (int d = 1; d < 32; d <<= 1) {
                int t = __shfl_up_sync(0xffffffff, w, d);
                if (lane >= d) w += t;
            }
            warpsum[lane] = w;
        }
        __syncthreads();
        int incl = x + (wid > 0 ? warpsum[wid - 1] : 0);
        int base = sBase;
        if (idx < N4) {
            int e0 = base + incl - s;
            int4 o;
            o.x = e0;
            o.y = e0 + v.x;
            o.z = o.y + v.y;
            o.w = o.z + v.z;
            rowptr4[idx] = o;
            cursor4[idx] = o;
        }
        __syncthreads();
        if (tid == 1023) sBase = base + incl;
        __syncthreads();
    }
}

__global__ void __launch_bounds__(256) fill_csr(
    const int* __restrict__ ei, int* __restrict__ cursor,
    int* __restrict__ csr, int E)
{
    int t = blockIdx.x * 256 + threadIdx.x;
    if (t >= E) return;
    int d = ei[E + t];
    int slot = atomicAdd(&cursor[d], 1);
    csr[slot] = ei[t];
}

// ---------------------------------------------------------------------------
// Dual GEMM. 4 rows x 4 cols x 2 mats per thread. Input rows broadcast (4
// movs), weight col-pairs come straight from LDS.128 (no movs). Forced to
// 2 blocks/SM so tile-load/sync bubbles overlap across blocks.
// acc[m][cp][j]: matrix m, column-pair cp (cols colq+32cp, colq+32cp+16... see
// permuted layout), row j.
// ---------------------------------------------------------------------------
template<int K>
__global__ void __launch_bounds__(256, 2) dual_gemm(
    const float* __restrict__ in,
    const float* __restrict__ Wr,  const float* __restrict__ Wo,
    float* __restrict__ y, float* __restrict__ r, int N)
{
    __shared__ float sIn[32][68];   // [k][row], row stride 272B (16B aligned)
    __shared__ float sWr[32][64];   // permuted: [k][q*4+c] = W[k][q+16c]
    __shared__ float sWo[32][64];

    const int tid  = threadIdx.x;
    const int colq = tid & 15;
    const int rowg = tid >> 4;          // 0..15 -> rows rowg*4 .. rowg*4+3
    const int row0 = blockIdx.x * 64;

    unsigned long long accY[2][4], accR[2][4];   // [colpair][row]
    #pragma unroll
    for (int cp = 0; cp < 2; cp++)
        #pragma unroll
        for (int j = 0; j < 4; j++) { accY[cp][j] = 0ull; accR[cp][j] = 0ull; }

    for (int kc = 0; kc < K; kc += 32) {
        __syncthreads();
        #pragma unroll
        for (int e = 0; e < 8; e++) {
            int linear = tid + e * 256;
            int rl = linear >> 5;
            int kl = linear & 31;
            int grow = row0 + rl;
            sIn[kl][rl] = (grow < N) ? in[(size_t)grow * K + kc + kl] : 0.f;
        }
        #pragma unroll
        for (int e = 0; e < 8; e++) {
            int linear = tid + e * 256;
            int kk = linear >> 6;
            int cc = linear & 63;
            int pos = (cc & 15) * 4 + (cc >> 4);
            sWr[kk][pos] = Wr[(size_t)(kc + kk) * HID + cc];
            sWo[kk][pos] = Wo[(size_t)(kc + kk) * HID + cc];
        }
        __syncthreads();

        #pragma unroll
        for (int k = 0; k < 32; k++) {
            // weight col-pairs directly from LDS.128 (ulonglong2 view)
            ulonglong2 wr = *(const ulonglong2*)(&sWr[k][colq * 4]);
            ulonglong2 wo = *(const ulonglong2*)(&sWo[k][colq * 4]);
            float4 av = *(const float4*)(&sIn[k][rowg * 4]);
            unsigned long long a0 = bcast2(av.x), a1 = bcast2(av.y);
            unsigned long long a2 = bcast2(av.z), a3 = bcast2(av.w);
            FMA2(accY[0][0], wr.x, a0);  FMA2(accY[1][0], wr.y, a0);
            FMA2(accY[0][1], wr.x, a1);  FMA2(accY[1][1], wr.y, a1);
            FMA2(accY[0][2], wr.x, a2);  FMA2(accY[1][2], wr.y, a2);
            FMA2(accY[0][3], wr.x, a3);  FMA2(accY[1][3], wr.y, a3);
            FMA2(accR[0][0], wo.x, a0);  FMA2(accR[1][0], wo.y, a0);
            FMA2(accR[0][1], wo.x, a1);  FMA2(accR[1][1], wo.y, a1);
            FMA2(accR[0][2], wo.x, a2);  FMA2(accR[1][2], wo.y, a2);
            FMA2(accR[0][3], wo.x, a3);  FMA2(accR[1][3], wo.y, a3);
        }
    }

    // acc[cp][j]: lo lane = col colq + 32*cp + 0, hi lane = col colq + 32*cp + 16
    const int rb = row0 + rowg * 4;
    #pragma unroll
    for (int cp = 0; cp < 2; cp++) {
        int cLo = colq + 32 * cp;
        int cHi = cLo + 16;
        #pragma unroll
        for (int j = 0; j < 4; j++) {
            int grow = rb + j;
            if (grow < N) {
                y[(size_t)grow * HID + cLo] = f2_lo(accY[cp][j]);
                y[(size_t)grow * HID + cHi] = f2_hi(accY[cp][j]);
                r[(size_t)grow * HID + cLo] = f2_lo(accR[cp][j]);
                r[(size_t)grow * HID + cHi] = f2_hi(accR[cp][j]);
            }
        }
    }
}

// ---------------------------------------------------------------------------
// CSR gather aggregation. 16 threads per node, register accumulation.
// MODE 0: all nodes,      out = relu(acc + r)   (in place over r)
// MODE 1: flagged nodes,  out = relu(acc + r)
// ---------------------------------------------------------------------------
template<int MODE>
__global__ void __launch_bounds__(256) gather_agg(
    const float4* __restrict__ y, const int* __restrict__ rowptr,
    const int* __restrict__ deg, const int* __restrict__ csr,
    const unsigned char* __restrict__ flag,
    float4* r_io, int N)
{
    int t = blockIdx.x * 256 + threadIdx.x;
    int node = t >> 4;
    if (node >= N) return;
    if (MODE == 1 && !flag[node]) return;
    int lane = t & 15;
    int start = rowptr[node];
    int end   = start + deg[node];

    float4 acc = make_float4(0.f, 0.f, 0.f, 0.f);
    int e = start;
    for (; e + 4 <= end; e += 4) {
        int s0 = csr[e], s1 = csr[e+1], s2 = csr[e+2], s3 = csr[e+3];
        float4 v0 = y[(size_t)s0 * 16 + lane];
        float4 v1 = y[(size_t)s1 * 16 + lane];
        float4 v2 = y[(size_t)s2 * 16 + lane];
        float4 v3 = y[(size_t)s3 * 16 + lane];
        acc.x += (v0.x + v1.x) + (v2.x + v3.x);
        acc.y += (v0.y + v1.y) + (v2.y + v3.y);
        acc.z += (v0.z + v1.z) + (v2.z + v3.z);
        acc.w += (v0.w + v1.w) + (v2.w + v3.w);
    }
    for (; e < end; e++) {
        float4 v = y[(size_t)csr[e] * 16 + lane];
        acc.x += v.x; acc.y += v.y; acc.z += v.z; acc.w += v.w;
    }

    size_t o = (size_t)node * 16 + lane;
    float4 b = r_io[o];
    b.x = fmaxf(acc.x + b.x, 0.f);
    b.y = fmaxf(acc.y + b.y, 0.f);
    b.z = fmaxf(acc.z + b.z, 0.f);
    b.w = fmaxf(acc.w + b.w, 0.f);
    r_io[o] = b;
}

// ---------------------------------------------------------------------------
// Layer 3 fused: graph-0 prefix tiles gather agg3 = sum h2[src] straight into
// smem, then h3 = relu(agg3@Wr + h2@Wo). Non-prefix tiles exit immediately.
// ---------------------------------------------------------------------------
__global__ void __launch_bounds__(256) gemm3_fused(
    const float4* __restrict__ h2_4, const float* __restrict__ h2,
    const float* __restrict__ Wr,  const float* __restrict__ Wo,
    const int* __restrict__ rowptr, const int* __restrict__ deg,
    const int* __restrict__ csr, const int* __restrict__ batch,
    float* __restrict__ h3, int N)
{
    const int row0 = blockIdx.x * 64;
    if (batch[row0] != 0) return;

    __shared__ float sA[64][68];    // gathered agg, [k][row], all K=64
    __shared__ float sB[32][68];    // h2 tile, [k][row]
    __shared__ float sWr[32][64];   // permuted
    __shared__ float sWo[32][64];   // permuted

    const int tid  = threadIdx.x;
    const int colq = tid & 15;
    const int rowg = tid >> 4;

    // ---- gather phase: 16 threads per node, 16 nodes per pass, 4 passes ----
    {
        int lane = tid & 15;
        int ng   = tid >> 4;
        #pragma unroll
        for (int pass = 0; pass < 4; pass++) {
            int row  = pass * 16 + ng;
            int grow = row0 + row;
            float4 acc = make_float4(0.f, 0.f, 0.f, 0.f);
            if (grow < N) {
                int start = rowptr[grow];
                int end   = start + deg[grow];
                for (int e = start; e < end; e++) {
                    float4 v = h2_4[(size_t)csr[e] * 16 + lane];
                    acc.x += v.x; acc.y += v.y; acc.z += v.z; acc.w += v.w;
                }
            }
            sA[lane * 4 + 0][row] = acc.x;
            sA[lane * 4 + 1][row] = acc.y;
            sA[lane * 4 + 2][row] = acc.z;
            sA[lane * 4 + 3][row] = acc.w;
        }
    }

    unsigned long long acc[2][4];
    #pragma unroll
    for (int cp = 0; cp < 2; cp++)
        #pragma unroll
        for (int j = 0; j < 4; j++) acc[cp][j] = 0ull;

    for (int kc = 0; kc < HID; kc += 32) {
        __syncthreads();
        #pragma unroll
        for (int e = 0; e < 8; e++) {
            int linear = tid + e * 256;
            int rl = linear >> 5;
            int kl = linear & 31;
            int grow = row0 + rl;
            sB[kl][rl] = (grow < N) ? h2[(size_t)grow * HID + kc + kl] : 0.f;
        }
        #pragma unroll
        for (int e = 0; e < 8; e++) {
            int linear = tid + e * 256;
            int kk = linear >> 6;
            int cc = linear & 63;
            int pos = (cc & 15) * 4 + (cc >> 4);
            sWr[kk][pos] = Wr[(size_t)(kc + kk) * HID + cc];
            sWo[kk][pos] = Wo[(size_t)(kc + kk) * HID + cc];
        }
        __syncthreads();

        #pragma unroll
        for (int k = 0; k < 32; k++) {
            ulonglong2 wr = *(const ulonglong2*)(&sWr[k][colq * 4]);
            ulonglong2 wo = *(const ulonglong2*)(&sWo[k][colq * 4]);
            float4 av = *(const float4*)(&sA[kc + k][rowg * 4]);
            float4 bv = *(const float4*)(&sB[k][rowg * 4]);
            unsigned long long a0 = bcast2(av.x), a1 = bcast2(av.y);
            unsigned long long a2 = bcast2(av.z), a3 = bcast2(av.w);
            unsigned long long b0 = bcast2(bv.x), b1 = bcast2(bv.y);
            unsigned long long b2 = bcast2(bv.z), b3 = bcast2(bv.w);
            FMA2(acc[0][0], wr.x, a0);  FMA2(acc[1][0], wr.y, a0);
            FMA2(acc[0][1], wr.x, a1);  FMA2(acc[1][1], wr.y, a1);
            FMA2(acc[0][2], wr.x, a2);  FMA2(acc[1][2], wr.y, a2);
            FMA2(acc[0][3], wr.x, a3);  FMA2(acc[1][3], wr.y, a3);
            FMA2(acc[0][0], wo.x, b0);  FMA2(acc[1][0], wo.y, b0);
            FMA2(acc[0][1], wo.x, b1);  FMA2(acc[1][1], wo.y, b1);
            FMA2(acc[0][2], wo.x, b2);  FMA2(acc[1][2], wo.y, b2);
            FMA2(acc[0][3], wo.x, b3);  FMA2(acc[1][3], wo.y, b3);
        }
    }

    const int rb = row0 + rowg * 4;
    #pragma unroll
    for (int cp = 0; cp < 2; cp++) {
        int cLo = colq + 32 * cp;
        int cHi = cLo + 16;
        #pragma unroll
        for (int j = 0; j < 4; j++) {
            int grow = rb + j;
            if (grow < N) {
                h3[(size_t)grow * HID + cLo] = fmaxf(f2_lo(acc[cp][j]), 0.f);
                h3[(size_t)grow * HID + cHi] = fmaxf(f2_hi(acc[cp][j]), 0.f);
            }
        }
    }
}

// ---------------------------------------------------------------------------
// Mean-pool graph 0, fc head, softmax
// ---------------------------------------------------------------------------
__global__ void __launch_bounds__(256) pool_head(
    const float* __restrict__ h, const int* __restrict__ batch,
    const float* __restrict__ Wfc, const float* __restrict__ bfc,
    float* __restrict__ out, int N)
{
    __shared__ float ssum[4][HID];
    __shared__ float scnt[4];
    __shared__ float smean[HID];
    __shared__ float slog[TYPE_NUM];

    int tid = threadIdx.x;
    int g = tid >> 6;
    int d = tid & 63;

    float acc = 0.f;
    int cnt = 0;
    for (int i = g; i < N; i += 4) {
        if (batch[i] != 0) break;
        acc += h[(size_t)i * HID + d];
        cnt++;
    }
    ssum[g][d] = acc;
    if (d == 0) scnt[g] = (float)cnt;
    __syncthreads();

    if (tid < HID) {
        float m = ssum[0][tid] + ssum[1][tid] + ssum[2][tid] + ssum[3][tid];
        float c = scnt[0] + scnt[1] + scnt[2] + scnt[3];
        smean[tid] = m / fmaxf(c, 1.f);
    }
    __syncthreads();

    if (tid < TYPE_NUM) {
        float l = bfc[tid];
        #pragma unroll
        for (int k = 0; k < HID; k++) l += smean[k] * Wfc[k * TYPE_NUM + tid];
        slog[tid] = l;
    }
    __syncthreads();

    if (tid == 0) {
        float mx = slog[0];
        #pragma unroll
        for (int j = 1; j < TYPE_NUM; j++) mx = fmaxf(mx, slog[j]);
        float s = 0.f;
        float ex[TYPE_NUM];
        #pragma unroll
        for (int j = 0; j < TYPE_NUM; j++) { ex[j] = __expf(slog[j] - mx); s += ex[j]; }
        float inv = 1.f / s;
        #pragma unroll
        for (int j = 0; j < TYPE_NUM; j++) out[j] = ex[j] * inv;
    }
}

// ---------------------------------------------------------------------------
extern "C" void kernel_launch(void* const* d_in, const int* in_sizes, int n_in,
                              void* d_out, int out_size)
{
    const float* x      = (const float*)d_in[0];
    const int*   ei     = (const int*)  d_in[1];
    const int*   batch  = (const int*)  d_in[2];
    const float* Wrel1  = (const float*)d_in[3];
    const float* Wroot1 = (const float*)d_in[4];
    const float* Wrel2  = (const float*)d_in[5];
    const float* Wroot2 = (const float*)d_in[6];
    const float* Wrel3  = (const float*)d_in[7];
    const float* Wroot3 = (const float*)d_in[8];
    const float* Wfc    = (const float*)d_in[9];
    const float* bfc    = (const float*)d_in[10];
    float* out = (float*)d_out;

    float4 *py4, *prA4, *prB4;
    unsigned char* pflag;
    int *pdeg, *prow, *pcur, *pcsr;
    cudaGetSymbolAddress((void**)&py4,   g_y);
    cudaGetSymbolAddress((void**)&prA4,  g_rA);
    cudaGetSymbolAddress((void**)&prB4,  g_rB);
    cudaGetSymbolAddress((void**)&pflag, g_flag);
    cudaGetSymbolAddress((void**)&pdeg,  g_deg);
    cudaGetSymbolAddress((void**)&prow,  g_rowptr);
    cudaGetSymbolAddress((void**)&pcur,  g_cursor);
    cudaGetSymbolAddress((void**)&pcsr,  g_csr);
    float* py  = (float*)py4;
    float* prA = (float*)prA4;
    float* prB = (float*)prB4;

    static cudaStream_t sSide = nullptr;
    static cudaEvent_t  evFork = nullptr, evJoin = nullptr;
    if (sSide == nullptr) {
        cudaStreamCreateWithFlags(&sSide, cudaStreamNonBlocking);
        cudaEventCreateWithFlags(&evFork, cudaEventDisableTiming);
        cudaEventCreateWithFlags(&evJoin, cudaEventDisableTiming);
    }

    const int N = N_NODES, E = N_EDGES;
    const int N4 = N / 4;
    const int nodeB = (N + 255) / 256;
    const int edgeB = (E + 255) / 256;
    const int gemmB = (N + 63) / 64;
    const int gathB = (N * 16 + 255) / 256;

    // ---- fork: CSR build on side stream, concurrent with gemm1 ----
    // Submission order keeps dual_gemm<FEAT> at launch slot #4 for ncu.
    cudaEventRecord(evFork, 0);
    cudaStreamWaitEvent(sSide, evFork, 0);
    node_init  <<<nodeB, 256, 0, sSide>>>(batch, pdeg, pflag, N);          // 1
    edge_hist  <<<edgeB, 256, 0, sSide>>>(ei, batch, pdeg, pflag, E);      // 2
    scan_rowptr<<<1, 1024, 0, sSide>>>((const int4*)pdeg, (int4*)prow,
                                       (int4*)pcur, N4);                   // 3
    dual_gemm<FEAT><<<gemmB, 256>>>(x, Wrel1, Wroot1, py, prA, N);         // 4 (profiled)
    fill_csr   <<<edgeB, 256, 0, sSide>>>(ei, pcur, pcsr, E);              // 5
    cudaEventRecord(evJoin, sSide);
    cudaStreamWaitEvent(0, evJoin, 0);

    // Layer 1 aggregate: h1 = relu(gather(y1) + rA)
    gather_agg<0><<<gathB, 256>>>(py4, prow, pdeg, pcsr, pflag, prA4, N);  // 6

    // Layer 2: y2 = h1@Wrel2, rB = h1@Wroot2; h2 = relu(gather(y2)+rB) on flagged
    dual_gemm<HID><<<gemmB, 256>>>(prA, Wrel2, Wroot2, py, prB, N);        // 7
    gather_agg<1><<<gathB, 256>>>(py4, prow, pdeg, pcsr, pflag, prB4, N);  // 8

    // Layer 3 fused gather+GEMM on graph-0 prefix
    gemm3_fused<<<gemmB, 256>>>(prB4, prB, Wrel3, Wroot3,
                                prow, pdeg, pcsr, batch, prA, N);          // 9

    // Head
    pool_head<<<1, 256>>>(prA, batch, Wfc, bfc, out, N);                   // 10
}

// round 14
// speedup vs baseline: 1.1729x; 1.0011x over previous
#include <cuda_runtime.h>
#include <cuda_bf16.h>
#include <math.h>

#define N_NODES 50000
#define N_EDGES 800000
#define FEAT    128
#define HID     64
#define TYPE_NUM 10

// ---------------- scratch buffers (float4-typed => 16B alignment) -----------
__device__ float4 g_y [N_NODES * HID / 4];   // transformed features
__device__ float4 g_rA[N_NODES * HID / 4];   // root part / h (ping)
__device__ float4 g_rB[N_NODES * HID / 4];   // root part / h (pong)
__device__ unsigned char g_flag[N_NODES];    // layer-2 active-node flags
__device__ int g_deg   [N_NODES];
__device__ int g_rowptr[N_NODES];
__device__ int g_cursor[N_NODES];
__device__ int g_csr   [N_EDGES];            // src node per CSR slot

// packed f32x2 helpers --------------------------------------------------------
#define FMA2(acc, a, b) \
    asm("fma.rn.f32x2 %0, %1, %2, %3;" : "=l"(acc) : "l"(a), "l"(b), "l"(acc))

__device__ __forceinline__ unsigned long long bcast2(float v) {
    unsigned long long r;
    unsigned u = __float_as_uint(v);
    asm("mov.b64 %0, {%1, %1};" : "=l"(r) : "r"(u));
    return r;
}
__device__ __forceinline__ float f2_lo(unsigned long long v) {
    return __uint_as_float((unsigned)v);
}
__device__ __forceinline__ float f2_hi(unsigned long long v) {
    return __uint_as_float((unsigned)(v >> 32));
}

// cp.async helpers ------------------------------------------------------------
__device__ __forceinline__ void cp4(void* dst, const void* src, int szbytes) {
    unsigned d = (unsigned)__cvta_generic_to_shared(dst);
    asm volatile("cp.async.ca.shared.global [%0], [%1], 4, %2;"
                 :: "r"(d), "l"(src), "r"(szbytes));
}
#define CP_COMMIT() asm volatile("cp.async.commit_group;")
#define CP_WAIT0()  asm volatile("cp.async.wait_group 0;")

// ---------------------------------------------------------------------------
// CSR build
// ---------------------------------------------------------------------------
__global__ void __launch_bounds__(256) node_init(
    const int* __restrict__ batch, int* __restrict__ deg,
    unsigned char* __restrict__ flag, int N)
{
    int t = blockIdx.x * 256 + threadIdx.x;
    if (t >= N) return;
    deg[t] = 0;
    flag[t] = (batch[t] == 0) ? 1 : 0;
}

__global__ void __launch_bounds__(256) edge_hist(
    const int* __restrict__ ei, const int* __restrict__ batch,
    int* __restrict__ deg, unsigned char* __restrict__ flag, int E)
{
    int t = blockIdx.x * 256 + threadIdx.x;
    if (t >= E) return;
    int s = ei[t];
    int d = ei[E + t];
    atomicAdd(&deg[d], 1);
    if (batch[d] == 0) flag[s] = 1;
}

// Single-block exclusive scan, 4 elems/thread (int4): 13 chunks for N=50000.
__global__ void __launch_bounds__(1024) scan_rowptr(
    const int4* __restrict__ deg4, int4* __restrict__ rowptr4,
    int4* __restrict__ cursor4, int N4)
{
    __shared__ int warpsum[32];
    __shared__ int sBase;
    const int tid  = threadIdx.x;
    const int lane = tid & 31;
    const int wid  = tid >> 5;
    if (tid == 0) sBase = 0;
    __syncthreads();
    const int nchunk = (N4 + 1023) >> 10;
    for (int c = 0; c < nchunk; c++) {
        int idx = (c << 10) + tid;
        int4 v = (idx < N4) ? deg4[idx] : make_int4(0, 0, 0, 0);
        int s = v.x + v.y + v.z + v.w;
        int x = s;
        #pragma unroll
        for (int d = 1; d < 32; d <<= 1) {
            int t = __shfl_up_sync(0xffffffff, x, d);
            if (lane >= d) x += t;
        }
        if (lane == 31) warpsum[wid] = x;
        __syncthreads();
        if (wid == 0) {
            int w = warpsum[lane];
            #pragma unroll
            for (int d = 1; d < 32; d <<= 1) {
                int t = __shfl_up_sync(0xffffffff, w, d);
                if (lane >= d) w += t;
            }
            warpsum[lane] = w;
        }
        __syncthreads();
        int incl = x + (wid > 0 ? warpsum[wid - 1] : 0);
        int base = sBase;
        if (idx < N4) {
            int e0 = base + incl - s;
            int4 o;
            o.x = e0;
            o.y = e0 + v.x;
            o.z = o.y + v.y;
            o.w = o.z + v.z;
            rowptr4[idx] = o;
            cursor4[idx] = o;
        }
        __syncthreads();
        if (tid == 1023) sBase = base + incl;
        __syncthreads();
    }
}

__global__ void __launch_bounds__(256) fill_csr(
    const int* __restrict__ ei, int* __restrict__ cursor,
    int* __restrict__ csr, int E)
{
    int t = blockIdx.x * 256 + threadIdx.x;
    if (t >= E) return;
    int d = ei[E + t];
    int slot = atomicAdd(&cursor[d], 1);
    csr[slot] = ei[t];
}

// ---------------------------------------------------------------------------
// Dual GEMM, software-pipelined:
//  - ALL weights (K x 64, both matrices, permuted) loaded once into smem
//  - input tile double-buffered via cp.async; prefetch overlaps compute
// Dynamic smem: 2*32*68 + 2*K*64 floats.
// ---------------------------------------------------------------------------
template<int K>
__global__ void __launch_bounds__(256, 2) dual_gemm(
    const float* __restrict__ in,
    const float* __restrict__ Wr,  const float* __restrict__ Wo,
    float* __restrict__ y, float* __restrict__ r, int N)
{
    extern __shared__ float smem[];
    float (*sIn)[32][68] = (float(*)[32][68])smem;           // [buf][k][row]
    float (*sWr)[64] = (float(*)[64])(smem + 2 * 32 * 68);   // [K][64] permuted
    float (*sWo)[64] = (float(*)[64])(smem + 2 * 32 * 68 + K * 64);

    const int tid  = threadIdx.x;
    const int colq = tid & 15;
    const int rowg = tid >> 4;          // 0..15 -> rows rowg*4 .. rowg*4+3
    const int row0 = blockIdx.x * 64;

    // ---- prologue: all weights + input tile 0, one cp.async group ----
    #pragma unroll
    for (int e = 0; e < K * 64 / 256; e++) {
        int linear = tid + e * 256;
        int kk = linear >> 6;
        int cc = linear & 63;
        int pos = (cc & 15) * 4 + (cc >> 4);
        cp4(&sWr[kk][pos], &Wr[(size_t)kk * HID + cc], 4);
        cp4(&sWo[kk][pos], &Wo[(size_t)kk * HID + cc], 4);
    }
    #pragma unroll
    for (int e = 0; e < 8; e++) {
        int linear = tid + e * 256;
        int rl = linear >> 5;
        int kl = linear & 31;
        int grow = row0 + rl;
        cp4(&sIn[0][kl][rl], &in[(size_t)grow * K + kl], grow < N ? 4 : 0);
    }
    CP_COMMIT();

    unsigned long long accY[2][4], accR[2][4];   // [colpair][row]
    #pragma unroll
    for (int cp = 0; cp < 2; cp++)
        #pragma unroll
        for (int j = 0; j < 4; j++) { accY[cp][j] = 0ull; accR[cp][j] = 0ull; }

    int buf = 0;
    for (int kc = 0; kc < K; kc += 32) {
        CP_WAIT0();
        __syncthreads();
        if (kc + 32 < K) {
            #pragma unroll
            for (int e = 0; e < 8; e++) {
                int linear = tid + e * 256;
                int rl = linear >> 5;
                int kl = linear & 31;
                int grow = row0 + rl;
                cp4(&sIn[buf ^ 1][kl][rl],
                    &in[(size_t)grow * K + kc + 32 + kl], grow < N ? 4 : 0);
            }
            CP_COMMIT();
        }

        #pragma unroll
        for (int k = 0; k < 32; k++) {
            ulonglong2 wr = *(const ulonglong2*)(&sWr[kc + k][colq * 4]);
            ulonglong2 wo = *(const ulonglong2*)(&sWo[kc + k][colq * 4]);
            float4 av = *(const float4*)(&sIn[buf][k][rowg * 4]);
            unsigned long long a0 = bcast2(av.x), a1 = bcast2(av.y);
            unsigned long long a2 = bcast2(av.z), a3 = bcast2(av.w);
            FMA2(accY[0][0], wr.x, a0);  FMA2(accY[1][0], wr.y, a0);
            FMA2(accY[0][1], wr.x, a1);  FMA2(accY[1][1], wr.y, a1);
            FMA2(accY[0][2], wr.x, a2);  FMA2(accY[1][2], wr.y, a2);
            FMA2(accY[0][3], wr.x, a3);  FMA2(accY[1][3], wr.y, a3);
            FMA2(accR[0][0], wo.x, a0);  FMA2(accR[1][0], wo.y, a0);
            FMA2(accR[0][1], wo.x, a1);  FMA2(accR[1][1], wo.y, a1);
            FMA2(accR[0][2], wo.x, a2);  FMA2(accR[1][2], wo.y, a2);
            FMA2(accR[0][3], wo.x, a3);  FMA2(accR[1][3], wo.y, a3);
        }
        buf ^= 1;
    }

    // acc[cp][j]: lo lane = col colq + 32*cp, hi lane = col colq + 32*cp + 16
    const int rb = row0 + rowg * 4;
    #pragma unroll
    for (int cp = 0; cp < 2; cp++) {
        int cLo = colq + 32 * cp;
        int cHi = cLo + 16;
        #pragma unroll
        for (int j = 0; j < 4; j++) {
            int grow = rb + j;
            if (grow < N) {
                y[(size_t)grow * HID + cLo] = f2_lo(accY[cp][j]);
                y[(size_t)grow * HID + cHi] = f2_hi(accY[cp][j]);
                r[(size_t)grow * HID + cLo] = f2_lo(accR[cp][j]);
                r[(size_t)grow * HID + cHi] = f2_hi(accR[cp][j]);
            }
        }
    }
}

static const int SMEM_GEMM1 = (2 * 32 * 68 + 2 * FEAT * 64) * 4;  // 82,944 B
static const int SMEM_GEMM2 = (2 * 32 * 68 + 2 * HID  * 64) * 4;  // 50,176 B

// ---------------------------------------------------------------------------
// CSR gather aggregation. 16 threads per node, register accumulation.
// MODE 0: all nodes,      out = relu(acc + r)   (in place over r)
// MODE 1: flagged nodes,  out = relu(acc + r)
// ---------------------------------------------------------------------------
template<int MODE>
__global__ void __launch_bounds__(256) gather_agg(
    const float4* __restrict__ y, const int* __restrict__ rowptr,
    const int* __restrict__ deg, const int* __restrict__ csr,
    const unsigned char* __restrict__ flag,
    float4* r_io, int N)
{
    int t = blockIdx.x * 256 + threadIdx.x;
    int node = t >> 4;
    if (node >= N) return;
    if (MODE == 1 && !flag[node]) return;
    int lane = t & 15;
    int start = rowptr[node];
    int end   = start + deg[node];

    float4 acc = make_float4(0.f, 0.f, 0.f, 0.f);
    int e = start;
    for (; e + 4 <= end; e += 4) {
        int s0 = csr[e], s1 = csr[e+1], s2 = csr[e+2], s3 = csr[e+3];
        float4 v0 = y[(size_t)s0 * 16 + lane];
        float4 v1 = y[(size_t)s1 * 16 + lane];
        float4 v2 = y[(size_t)s2 * 16 + lane];
        float4 v3 = y[(size_t)s3 * 16 + lane];
        acc.x += (v0.x + v1.x) + (v2.x + v3.x);
        acc.y += (v0.y + v1.y) + (v2.y + v3.y);
        acc.z += (v0.z + v1.z) + (v2.z + v3.z);
        acc.w += (v0.w + v1.w) + (v2.w + v3.w);
    }
    for (; e < end; e++) {
        float4 v = y[(size_t)csr[e] * 16 + lane];
        acc.x += v.x; acc.y += v.y; acc.z += v.z; acc.w += v.w;
    }

    size_t o = (size_t)node * 16 + lane;
    float4 b = r_io[o];
    b.x = fmaxf(acc.x + b.x, 0.f);
    b.y = fmaxf(acc.y + b.y, 0.f);
    b.z = fmaxf(acc.z + b.z, 0.f);
    b.w = fmaxf(acc.w + b.w, 0.f);
    r_io[o] = b;
}

// ---------------------------------------------------------------------------
// Layer 3 fused: graph-0 prefix tiles gather agg3 = sum h2[src] straight into
// smem, then h3 = relu(agg3@Wr + h2@Wo). Non-prefix tiles exit immediately.
// ---------------------------------------------------------------------------
__global__ void __launch_bounds__(256) gemm3_fused(
    const float4* __restrict__ h2_4, const float* __restrict__ h2,
    const float* __restrict__ Wr,  const float* __restrict__ Wo,
    const int* __restrict__ rowptr, const int* __restrict__ deg,
    const int* __restrict__ csr, const int* __restrict__ batch,
    float* __restrict__ h3, int N)
{
    const int row0 = blockIdx.x * 64;
    if (batch[row0] != 0) return;

    __shared__ float sA[64][68];    // gathered agg, [k][row], all K=64
    __shared__ float sB[32][68];    // h2 tile, [k][row]
    __shared__ float sWr[32][64];   // permuted
    __shared__ float sWo[32][64];   // permuted

    const int tid  = threadIdx.x;
    const int colq = tid & 15;
    const int rowg = tid >> 4;

    // ---- gather phase: 16 threads per node, 16 nodes per pass, 4 passes ----
    {
        int lane = tid & 15;
        int ng   = tid >> 4;
        #pragma unroll
        for (int pass = 0; pass < 4; pass++) {
            int row  = pass * 16 + ng;
            int grow = row0 + row;
            float4 acc = make_float4(0.f, 0.f, 0.f, 0.f);
            if (grow < N) {
                int start = rowptr[grow];
                int end   = start + deg[grow];
                for (int e = start; e < end; e++) {
                    float4 v = h2_4[(size_t)csr[e] * 16 + lane];
                    acc.x += v.x; acc.y += v.y; acc.z += v.z; acc.w += v.w;
                }
            }
            sA[lane * 4 + 0][row] = acc.x;
            sA[lane * 4 + 1][row] = acc.y;
            sA[lane * 4 + 2][row] = acc.z;
            sA[lane * 4 + 3][row] = acc.w;
        }
    }

    unsigned long long acc[2][4];
    #pragma unroll
    for (int cp = 0; cp < 2; cp++)
        #pragma unroll
        for (int j = 0; j < 4; j++) acc[cp][j] = 0ull;

    for (int kc = 0; kc < HID; kc += 32) {
        __syncthreads();
        #pragma unroll
        for (int e = 0; e < 8; e++) {
            int linear = tid + e * 256;
            int rl = linear >> 5;
            int kl = linear & 31;
            int grow = row0 + rl;
            sB[kl][rl] = (grow < N) ? h2[(size_t)grow * HID + kc + kl] : 0.f;
        }
        #pragma unroll
        for (int e = 0; e < 8; e++) {
            int linear = tid + e * 256;
            int kk = linear >> 6;
            int cc = linear & 63;
            int pos = (cc & 15) * 4 + (cc >> 4);
            sWr[kk][pos] = Wr[(size_t)(kc + kk) * HID + cc];
            sWo[kk][pos] = Wo[(size_t)(kc + kk) * HID + cc];
        }
        __syncthreads();

        #pragma unroll
        for (int k = 0; k < 32; k++) {
            ulonglong2 wr = *(const ulonglong2*)(&sWr[k][colq * 4]);
            ulonglong2 wo = *(const ulonglong2*)(&sWo[k][colq * 4]);
            float4 av = *(const float4*)(&sA[kc + k][rowg * 4]);
            float4 bv = *(const float4*)(&sB[k][rowg * 4]);
            unsigned long long a0 = bcast2(av.x), a1 = bcast2(av.y);
            unsigned long long a2 = bcast2(av.z), a3 = bcast2(av.w);
            unsigned long long b0 = bcast2(bv.x), b1 = bcast2(bv.y);
            unsigned long long b2 = bcast2(bv.z), b3 = bcast2(bv.w);
            FMA2(acc[0][0], wr.x, a0);  FMA2(acc[1][0], wr.y, a0);
            FMA2(acc[0][1], wr.x, a1);  FMA2(acc[1][1], wr.y, a1);
            FMA2(acc[0][2], wr.x, a2);  FMA2(acc[1][2], wr.y, a2);
            FMA2(acc[0][3], wr.x, a3);  FMA2(acc[1][3], wr.y, a3);
            FMA2(acc[0][0], wo.x, b0);  FMA2(acc[1][0], wo.y, b0);
            FMA2(acc[0][1], wo.x, b1);  FMA2(acc[1][1], wo.y, b1);
            FMA2(acc[0][2], wo.x, b2);  FMA2(acc[1][2], wo.y, b2);
            FMA2(acc[0][3], wo.x, b3);  FMA2(acc[1][3], wo.y, b3);
        }
    }

    const int rb = row0 + rowg * 4;
    #pragma unroll
    for (int cp = 0; cp < 2; cp++) {
        int cLo = colq + 32 * cp;
        int cHi = cLo + 16;
        #pragma unroll
        for (int j = 0; j < 4; j++) {
            int grow = rb + j;
            if (grow < N) {
                h3[(size_t)grow * HID + cLo] = fmaxf(f2_lo(acc[cp][j]), 0.f);
                h3[(size_t)grow * HID + cHi] = fmaxf(f2_hi(acc[cp][j]), 0.f);
            }
        }
    }
}

// ---------------------------------------------------------------------------
// Mean-pool graph 0, fc head, softmax
// ---------------------------------------------------------------------------
__global__ void __launch_bounds__(256) pool_head(
    const float* __restrict__ h, const int* __restrict__ batch,
    const float* __restrict__ Wfc, const float* __restrict__ bfc,
    float* __restrict__ out, int N)
{
    __shared__ float ssum[4][HID];
    __shared__ float scnt[4];
    __shared__ float smean[HID];
    __shared__ float slog[TYPE_NUM];

    int tid = threadIdx.x;
    int g = tid >> 6;
    int d = tid & 63;

    float acc = 0.f;
    int cnt = 0;
    for (int i = g; i < N; i += 4) {
        if (batch[i] != 0) break;
        acc += h[(size_t)i * HID + d];
        cnt++;
    }
    ssum[g][d] = acc;
    if (d == 0) scnt[g] = (float)cnt;
    __syncthreads();

    if (tid < HID) {
        float m = ssum[0][tid] + ssum[1][tid] + ssum[2][tid] + ssum[3][tid];
        float c = scnt[0] + scnt[1] + scnt[2] + scnt[3];
        smean[tid] = m / fmaxf(c, 1.f);
    }
    __syncthreads();

    if (tid < TYPE_NUM) {
        float l = bfc[tid];
        #pragma unroll
        for (int k = 0; k < HID; k++) l += smean[k] * Wfc[k * TYPE_NUM + tid];
        slog[tid] = l;
    }
    __syncthreads();

    if (tid == 0) {
        float mx = slog[0];
        #pragma unroll
        for (int j = 1; j < TYPE_NUM; j++) mx = fmaxf(mx, slog[j]);
        float s = 0.f;
        float ex[TYPE_NUM];
        #pragma unroll
        for (int j = 0; j < TYPE_NUM; j++) { ex[j] = __expf(slog[j] - mx); s += ex[j]; }
        float inv = 1.f / s;
        #pragma unroll
        for (int j = 0; j < TYPE_NUM; j++) out[j] = ex[j] * inv;
    }
}

// ---------------------------------------------------------------------------
extern "C" void kernel_launch(void* const* d_in, const int* in_sizes, int n_in,
                              void* d_out, int out_size)
{
    const float* x      = (const float*)d_in[0];
    const int*   ei     = (const int*)  d_in[1];
    const int*   batch  = (const int*)  d_in[2];
    const float* Wrel1  = (const float*)d_in[3];
    const float* Wroot1 = (const float*)d_in[4];
    const float* Wrel2  = (const float*)d_in[5];
    const float* Wroot2 = (const float*)d_in[6];
    const float* Wrel3  = (const float*)d_in[7];
    const float* Wroot3 = (const float*)d_in[8];
    const float* Wfc    = (const float*)d_in[9];
    const float* bfc    = (const float*)d_in[10];
    float* out = (float*)d_out;

    float4 *py4, *prA4, *prB4;
    unsigned char* pflag;
    int *pdeg, *prow, *pcur, *pcsr;
    cudaGetSymbolAddress((void**)&py4,   g_y);
    cudaGetSymbolAddress((void**)&prA4,  g_rA);
    cudaGetSymbolAddress((void**)&prB4,  g_rB);
    cudaGetSymbolAddress((void**)&pflag, g_flag);
    cudaGetSymbolAddress((void**)&pdeg,  g_deg);
    cudaGetSymbolAddress((void**)&prow,  g_rowptr);
    cudaGetSymbolAddress((void**)&pcur,  g_cursor);
    cudaGetSymbolAddress((void**)&pcsr,  g_csr);
    float* py  = (float*)py4;
    float* prA = (float*)prA4;
    float* prB = (float*)prB4;

    static cudaStream_t sSide = nullptr;
    static cudaEvent_t  evFork = nullptr, evJoin = nullptr;
    if (sSide == nullptr) {
        cudaStreamCreateWithFlags(&sSide, cudaStreamNonBlocking);
        cudaEventCreateWithFlags(&evFork, cudaEventDisableTiming);
        cudaEventCreateWithFlags(&evJoin, cudaEventDisableTiming);
        cudaFuncSetAttribute(dual_gemm<FEAT>,
                             cudaFuncAttributeMaxDynamicSharedMemorySize,
                             SMEM_GEMM1);
        cudaFuncSetAttribute(dual_gemm<HID>,
                             cudaFuncAttributeMaxDynamicSharedMemorySize,
                             SMEM_GEMM2);
    }

    const int N = N_NODES, E = N_EDGES;
    const int N4 = N / 4;
    const int nodeB = (N + 255) / 256;
    const int edgeB = (E + 255) / 256;
    const int gemmB = (N + 63) / 64;
    const int gathB = (N * 16 + 255) / 256;

    // ---- fork: CSR build on side stream, concurrent with gemm1 ----
    // Submission order keeps dual_gemm<FEAT> at launch slot #4 for ncu.
    cudaEventRecord(evFork, 0);
    cudaStreamWaitEvent(sSide, evFork, 0);
    node_init  <<<nodeB, 256, 0, sSide>>>(batch, pdeg, pflag, N);          // 1
    edge_hist  <<<edgeB, 256, 0, sSide>>>(ei, batch, pdeg, pflag, E);      // 2
    scan_rowptr<<<1, 1024, 0, sSide>>>((const int4*)pdeg, (int4*)prow,
                                       (int4*)pcur, N4);                   // 3
    dual_gemm<FEAT><<<gemmB, 256, SMEM_GEMM1>>>(x, Wrel1, Wroot1,
                                                py, prA, N);               // 4 (profiled)
    fill_csr   <<<edgeB, 256, 0, sSide>>>(ei, pcur, pcsr, E);              // 5
    cudaEventRecord(evJoin, sSide);
    cudaStreamWaitEvent(0, evJoin, 0);

    // Layer 1 aggregate: h1 = relu(gather(y1) + rA)
    gather_agg<0><<<gathB, 256>>>(py4, prow, pdeg, pcsr, pflag, prA4, N);  // 6

    // Layer 2: y2 = h1@Wrel2, rB = h1@Wroot2; h2 = relu(gather(y2)+rB) on flagged
    dual_gemm<HID><<<gemmB, 256, SMEM_GEMM2>>>(prA, Wrel2, Wroot2,
                                               py, prB, N);                // 7
    gather_agg<1><<<gathB, 256>>>(py4, prow, pdeg, pcsr, pflag, prB4, N);  // 8

    // Layer 3 fused gather+GEMM on graph-0 prefix
    gemm3_fused<<<gemmB, 256>>>(prB4, prB, Wrel3, Wroot3,
                                prow, pdeg, pcsr, batch, prA, N);          // 9

    // Head
    pool_head<<<1, 256>>>(prA, batch, Wfc, bfc, out, N);                   // 10
}

// round 15
// speedup vs baseline: 1.1845x; 1.0099x over previous
#include <cuda_runtime.h>
#include <cuda_bf16.h>
#include <math.h>

#define N_NODES 50000
#define N_EDGES 800000
#define FEAT    128
#define HID     64
#define TYPE_NUM 10

// ---------------- scratch buffers (float4-typed => 16B alignment) -----------
__device__ float4 g_y [N_NODES * HID / 4];   // transformed features
__device__ float4 g_rA[N_NODES * HID / 4];   // root part / h (ping)
__device__ float4 g_rB[N_NODES * HID / 4];   // root part / h (pong)
__device__ unsigned char g_flag[N_NODES];    // layer-2 active-node flags
__device__ int g_deg   [N_NODES];
__device__ int g_rowptr[N_NODES];
__device__ int g_cursor[N_NODES];
__device__ int g_csr   [N_EDGES];            // src node per CSR slot

// packed f32x2 helpers --------------------------------------------------------
#define FMA2(acc, a, b) \
    asm("fma.rn.f32x2 %0, %1, %2, %3;" : "=l"(acc) : "l"(a), "l"(b), "l"(acc))

__device__ __forceinline__ unsigned long long bcast2(float v) {
    unsigned long long r;
    unsigned u = __float_as_uint(v);
    asm("mov.b64 %0, {%1, %1};" : "=l"(r) : "r"(u));
    return r;
}
__device__ __forceinline__ float f2_lo(unsigned long long v) {
    return __uint_as_float((unsigned)v);
}
__device__ __forceinline__ float f2_hi(unsigned long long v) {
    return __uint_as_float((unsigned)(v >> 32));
}

// cp.async helpers ------------------------------------------------------------
__device__ __forceinline__ void cp4(void* dst, const void* src, int szbytes) {
    unsigned d = (unsigned)__cvta_generic_to_shared(dst);
    asm volatile("cp.async.ca.shared.global [%0], [%1], 4, %2;"
                 :: "r"(d), "l"(src), "r"(szbytes));
}
#define CP_COMMIT() asm volatile("cp.async.commit_group;")
#define CP_WAIT0()  asm volatile("cp.async.wait_group 0;")

// ---------------------------------------------------------------------------
// CSR build
// ---------------------------------------------------------------------------
__global__ void __launch_bounds__(256) node_init(
    const int* __restrict__ batch, int* __restrict__ deg,
    unsigned char* __restrict__ flag, int N)
{
    int t = blockIdx.x * 256 + threadIdx.x;
    if (t >= N) return;
    deg[t] = 0;
    flag[t] = (batch[t] == 0) ? 1 : 0;
}

__global__ void __launch_bounds__(256) edge_hist(
    const int* __restrict__ ei, const int* __restrict__ batch,
    int* __restrict__ deg, unsigned char* __restrict__ flag, int E)
{
    int t = blockIdx.x * 256 + threadIdx.x;
    if (t >= E) return;
    int s = ei[t];
    int d = ei[E + t];
    atomicAdd(&deg[d], 1);
    if (batch[d] == 0) flag[s] = 1;
}

// Single-block exclusive scan, 4 elems/thread (int4): 13 chunks for N=50000.
__global__ void __launch_bounds__(1024) scan_rowptr(
    const int4* __restrict__ deg4, int4* __restrict__ rowptr4,
    int4* __restrict__ cursor4, int N4)
{
    __shared__ int warpsum[32];
    __shared__ int sBase;
    const int tid  = threadIdx.x;
    const int lane = tid & 31;
    const int wid  = tid >> 5;
    if (tid == 0) sBase = 0;
    __syncthreads();
    const int nchunk = (N4 + 1023) >> 10;
    for (int c = 0; c < nchunk; c++) {
        int idx = (c << 10) + tid;
        int4 v = (idx < N4) ? deg4[idx] : make_int4(0, 0, 0, 0);
        int s = v.x + v.y + v.z + v.w;
        int x = s;
        #pragma unroll
        for (int d = 1; d < 32; d <<= 1) {
            int t = __shfl_up_sync(0xffffffff, x, d);
            if (lane >= d) x += t;
        }
        if (lane == 31) warpsum[wid] = x;
        __syncthreads();
        if (wid == 0) {
            int w = warpsum[lane];
            #pragma unroll
            for (int d = 1; d < 32; d <<= 1) {
                int t = __shfl_up_sync(0xffffffff, w, d);
                if (lane >= d) w += t;
            }
            warpsum[lane] = w;
        }
        __syncthreads();
        int incl = x + (wid > 0 ? warpsum[wid - 1] : 0);
        int base = sBase;
        if (idx < N4) {
            int e0 = base + incl - s;
            int4 o;
            o.x = e0;
            o.y = e0 + v.x;
            o.z = o.y + v.y;
            o.w = o.z + v.z;
            rowptr4[idx] = o;
            cursor4[idx] = o;
        }
        __syncthreads();
        if (tid == 1023) sBase = base + incl;
        __syncthreads();
    }
}

__global__ void __launch_bounds__(256) fill_csr(
    const int* __restrict__ ei, int* __restrict__ cursor,
    int* __restrict__ csr, int E)
{
    int t = blockIdx.x * 256 + threadIdx.x;
    if (t >= E) return;
    int d = ei[E + t];
    int slot = atomicAdd(&cursor[d], 1);
    csr[slot] = ei[t];
}

// ---------------------------------------------------------------------------
// Dual GEMM, 8 rows x 4 cols x 2 mats per thread (128-row tiles):
//  - weights loaded once per block (smem), 32B of weight LDS feeds 64 FMAs
//  - input tile double-buffered via cp.async
// Dynamic smem: 2*32*136 + 2*K*64 floats.
// ---------------------------------------------------------------------------
template<int K>
__global__ void __launch_bounds__(256, 2) dual_gemm(
    const float* __restrict__ in,
    const float* __restrict__ Wr,  const float* __restrict__ Wo,
    float* __restrict__ y, float* __restrict__ r, int N)
{
    extern __shared__ float smem[];
    float (*sIn)[32][136] = (float(*)[32][136])smem;          // [buf][k][row]
    float (*sWr)[64] = (float(*)[64])(smem + 2 * 32 * 136);   // [K][64] permuted
    float (*sWo)[64] = (float(*)[64])(smem + 2 * 32 * 136 + K * 64);

    const int tid  = threadIdx.x;
    const int colq = tid & 15;
    const int rowg = tid >> 4;          // 0..15 -> rows rowg*8 .. rowg*8+7
    const int row0 = blockIdx.x * 128;

    // ---- prologue: all weights + input tile 0, one cp.async group ----
    #pragma unroll
    for (int e = 0; e < K / 4; e++) {
        int linear = tid + e * 256;
        int kk = linear >> 6;
        int cc = linear & 63;
        int pos = (cc & 15) * 4 + (cc >> 4);
        cp4(&sWr[kk][pos], &Wr[(size_t)kk * HID + cc], 4);
        cp4(&sWo[kk][pos], &Wo[(size_t)kk * HID + cc], 4);
    }
    #pragma unroll
    for (int e = 0; e < 16; e++) {
        int linear = tid + e * 256;
        int rl = linear >> 5;
        int kl = linear & 31;
        int grow = row0 + rl;
        cp4(&sIn[0][kl][rl], &in[(size_t)grow * K + kl], grow < N ? 4 : 0);
    }
    CP_COMMIT();

    unsigned long long accY[2][8], accR[2][8];   // [colpair][row]
    #pragma unroll
    for (int cp = 0; cp < 2; cp++)
        #pragma unroll
        for (int j = 0; j < 8; j++) { accY[cp][j] = 0ull; accR[cp][j] = 0ull; }

    int buf = 0;
    for (int kc = 0; kc < K; kc += 32) {
        CP_WAIT0();
        __syncthreads();
        if (kc + 32 < K) {
            #pragma unroll
            for (int e = 0; e < 16; e++) {
                int linear = tid + e * 256;
                int rl = linear >> 5;
                int kl = linear & 31;
                int grow = row0 + rl;
                cp4(&sIn[buf ^ 1][kl][rl],
                    &in[(size_t)grow * K + kc + 32 + kl], grow < N ? 4 : 0);
            }
            CP_COMMIT();
        }

        #pragma unroll
        for (int k = 0; k < 32; k++) {
            ulonglong2 wr = *(const ulonglong2*)(&sWr[kc + k][colq * 4]);
            ulonglong2 wo = *(const ulonglong2*)(&sWo[kc + k][colq * 4]);
            float4 av0 = *(const float4*)(&sIn[buf][k][rowg * 8]);
            float4 av1 = *(const float4*)(&sIn[buf][k][rowg * 8 + 4]);
            unsigned long long a0 = bcast2(av0.x), a1 = bcast2(av0.y);
            unsigned long long a2 = bcast2(av0.z), a3 = bcast2(av0.w);
            unsigned long long a4 = bcast2(av1.x), a5 = bcast2(av1.y);
            unsigned long long a6 = bcast2(av1.z), a7 = bcast2(av1.w);
            FMA2(accY[0][0], wr.x, a0);  FMA2(accY[1][0], wr.y, a0);
            FMA2(accY[0][1], wr.x, a1);  FMA2(accY[1][1], wr.y, a1);
            FMA2(accY[0][2], wr.x, a2);  FMA2(accY[1][2], wr.y, a2);
            FMA2(accY[0][3], wr.x, a3);  FMA2(accY[1][3], wr.y, a3);
            FMA2(accY[0][4], wr.x, a4);  FMA2(accY[1][4], wr.y, a4);
            FMA2(accY[0][5], wr.x, a5);  FMA2(accY[1][5], wr.y, a5);
            FMA2(accY[0][6], wr.x, a6);  FMA2(accY[1][6], wr.y, a6);
            FMA2(accY[0][7], wr.x, a7);  FMA2(accY[1][7], wr.y, a7);
            FMA2(accR[0][0], wo.x, a0);  FMA2(accR[1][0], wo.y, a0);
            FMA2(accR[0][1], wo.x, a1);  FMA2(accR[1][1], wo.y, a1);
            FMA2(accR[0][2], wo.x, a2);  FMA2(accR[1][2], wo.y, a2);
            FMA2(accR[0][3], wo.x, a3);  FMA2(accR[1][3], wo.y, a3);
            FMA2(accR[0][4], wo.x, a4);  FMA2(accR[1][4], wo.y, a4);
            FMA2(accR[0][5], wo.x, a5);  FMA2(accR[1][5], wo.y, a5);
            FMA2(accR[0][6], wo.x, a6);  FMA2(accR[1][6], wo.y, a6);
            FMA2(accR[0][7], wo.x, a7);  FMA2(accR[1][7], wo.y, a7);
        }
        buf ^= 1;
    }

    // acc[cp][j]: lo lane = col colq + 32*cp, hi lane = col colq + 32*cp + 16
    const int rb = row0 + rowg * 8;
    #pragma unroll
    for (int cp = 0; cp < 2; cp++) {
        int cLo = colq + 32 * cp;
        int cHi = cLo + 16;
        #pragma unroll
        for (int j = 0; j < 8; j++) {
            int grow = rb + j;
            if (grow < N) {
                y[(size_t)grow * HID + cLo] = f2_lo(accY[cp][j]);
                y[(size_t)grow * HID + cHi] = f2_hi(accY[cp][j]);
                r[(size_t)grow * HID + cLo] = f2_lo(accR[cp][j]);
                r[(size_t)grow * HID + cHi] = f2_hi(accR[cp][j]);
            }
        }
    }
}

static const int SMEM_GEMM1 = (2 * 32 * 136 + 2 * FEAT * 64) * 4;  // 100,352 B
static const int SMEM_GEMM2 = (2 * 32 * 136 + 2 * HID  * 64) * 4;  //  67,584 B

// ---------------------------------------------------------------------------
// CSR gather aggregation. 16 threads per node, register accumulation.
// MODE 0: all nodes,      out = relu(acc + r)   (in place over r)
// MODE 1: flagged nodes,  out = relu(acc + r)
// ---------------------------------------------------------------------------
template<int MODE>
__global__ void __launch_bounds__(256) gather_agg(
    const float4* __restrict__ y, const int* __restrict__ rowptr,
    const int* __restrict__ deg, const int* __restrict__ csr,
    const unsigned char* __restrict__ flag,
    float4* r_io, int N)
{
    int t = blockIdx.x * 256 + threadIdx.x;
    int node = t >> 4;
    if (node >= N) return;
    if (MODE == 1 && !flag[node]) return;
    int lane = t & 15;
    int start = rowptr[node];
    int end   = start + deg[node];

    float4 acc = make_float4(0.f, 0.f, 0.f, 0.f);
    int e = start;
    for (; e + 4 <= end; e += 4) {
        int s0 = csr[e], s1 = csr[e+1], s2 = csr[e+2], s3 = csr[e+3];
        float4 v0 = y[(size_t)s0 * 16 + lane];
        float4 v1 = y[(size_t)s1 * 16 + lane];
        float4 v2 = y[(size_t)s2 * 16 + lane];
        float4 v3 = y[(size_t)s3 * 16 + lane];
        acc.x += (v0.x + v1.x) + (v2.x + v3.x);
        acc.y += (v0.y + v1.y) + (v2.y + v3.y);
        acc.z += (v0.z + v1.z) + (v2.z + v3.z);
        acc.w += (v0.w + v1.w) + (v2.w + v3.w);
    }
    for (; e < end; e++) {
        float4 v = y[(size_t)csr[e] * 16 + lane];
        acc.x += v.x; acc.y += v.y; acc.z += v.z; acc.w += v.w;
    }

    size_t o = (size_t)node * 16 + lane;
    float4 b = r_io[o];
    b.x = fmaxf(acc.x + b.x, 0.f);
    b.y = fmaxf(acc.y + b.y, 0.f);
    b.z = fmaxf(acc.z + b.z, 0.f);
    b.w = fmaxf(acc.w + b.w, 0.f);
    r_io[o] = b;
}

// ---------------------------------------------------------------------------
// Layer 3 fused: graph-0 prefix tiles gather agg3 = sum h2[src] straight into
// smem, then h3 = relu(agg3@Wr + h2@Wo). Non-prefix tiles exit immediately.
// ---------------------------------------------------------------------------
__global__ void __launch_bounds__(256) gemm3_fused(
    const float4* __restrict__ h2_4, const float* __restrict__ h2,
    const float* __restrict__ Wr,  const float* __restrict__ Wo,
    const int* __restrict__ rowptr, const int* __restrict__ deg,
    const int* __restrict__ csr, const int* __restrict__ batch,
    float* __restrict__ h3, int N)
{
    const int row0 = blockIdx.x * 64;
    if (batch[row0] != 0) return;

    __shared__ float sA[64][68];    // gathered agg, [k][row], all K=64
    __shared__ float sB[32][68];    // h2 tile, [k][row]
    __shared__ float sWr[32][64];   // permuted
    __shared__ float sWo[32][64];   // permuted

    const int tid  = threadIdx.x;
    const int colq = tid & 15;
    const int rowg = tid >> 4;

    // ---- gather phase: 16 threads per node, 16 nodes per pass, 4 passes ----
    {
        int lane = tid & 15;
        int ng   = tid >> 4;
        #pragma unroll
        for (int pass = 0; pass < 4; pass++) {
            int row  = pass * 16 + ng;
            int grow = row0 + row;
            float4 acc = make_float4(0.f, 0.f, 0.f, 0.f);
            if (grow < N) {
                int start = rowptr[grow];
                int end   = start + deg[grow];
                for (int e = start; e < end; e++) {
                    float4 v = h2_4[(size_t)csr[e] * 16 + lane];
                    acc.x += v.x; acc.y += v.y; acc.z += v.z; acc.w += v.w;
                }
            }
            sA[lane * 4 + 0][row] = acc.x;
            sA[lane * 4 + 1][row] = acc.y;
            sA[lane * 4 + 2][row] = acc.z;
            sA[lane * 4 + 3][row] = acc.w;
        }
    }

    unsigned long long acc[2][4];
    #pragma unroll
    for (int cp = 0; cp < 2; cp++)
        #pragma unroll
        for (int j = 0; j < 4; j++) acc[cp][j] = 0ull;

    for (int kc = 0; kc < HID; kc += 32) {
        __syncthreads();
        #pragma unroll
        for (int e = 0; e < 8; e++) {
            int linear = tid + e * 256;
            int rl = linear >> 5;
            int kl = linear & 31;
            int grow = row0 + rl;
            sB[kl][rl] = (grow < N) ? h2[(size_t)grow * HID + kc + kl] : 0.f;
        }
        #pragma unroll
        for (int e = 0; e < 8; e++) {
            int linear = tid + e * 256;
            int kk = linear >> 6;
            int cc = linear & 63;
            int pos = (cc & 15) * 4 + (cc >> 4);
            sWr[kk][pos] = Wr[(size_t)(kc + kk) * HID + cc];
            sWo[kk][pos] = Wo[(size_t)(kc + kk) * HID + cc];
        }
        __syncthreads();

        #pragma unroll
        for (int k = 0; k < 32; k++) {
            ulonglong2 wr = *(const ulonglong2*)(&sWr[k][colq * 4]);
            ulonglong2 wo = *(const ulonglong2*)(&sWo[k][colq * 4]);
            float4 av = *(const float4*)(&sA[kc + k][rowg * 4]);
            float4 bv = *(const float4*)(&sB[k][rowg * 4]);
            unsigned long long a0 = bcast2(av.x), a1 = bcast2(av.y);
            unsigned long long a2 = bcast2(av.z), a3 = bcast2(av.w);
            unsigned long long b0 = bcast2(bv.x), b1 = bcast2(bv.y);
            unsigned long long b2 = bcast2(bv.z), b3 = bcast2(bv.w);
            FMA2(acc[0][0], wr.x, a0);  FMA2(acc[1][0], wr.y, a0);
            FMA2(acc[0][1], wr.x, a1);  FMA2(acc[1][1], wr.y, a1);
            FMA2(acc[0][2], wr.x, a2);  FMA2(acc[1][2], wr.y, a2);
            FMA2(acc[0][3], wr.x, a3);  FMA2(acc[1][3], wr.y, a3);
            FMA2(acc[0][0], wo.x, b0);  FMA2(acc[1][0], wo.y, b0);
            FMA2(acc[0][1], wo.x, b1);  FMA2(acc[1][1], wo.y, b1);
            FMA2(acc[0][2], wo.x, b2);  FMA2(acc[1][2], wo.y, b2);
            FMA2(acc[0][3], wo.x, b3);  FMA2(acc[1][3], wo.y, b3);
        }
    }

    const int rb = row0 + rowg * 4;
    #pragma unroll
    for (int cp = 0; cp < 2; cp++) {
        int cLo = colq + 32 * cp;
        int cHi = cLo + 16;
        #pragma unroll
        for (int j = 0; j < 4; j++) {
            int grow = rb + j;
            if (grow < N) {
                h3[(size_t)grow * HID + cLo] = fmaxf(f2_lo(acc[cp][j]), 0.f);
                h3[(size_t)grow * HID + cHi] = fmaxf(f2_hi(acc[cp][j]), 0.f);
            }
        }
    }
}

// ---------------------------------------------------------------------------
// Mean-pool graph 0, fc head, softmax
// ---------------------------------------------------------------------------
__global__ void __launch_bounds__(256) pool_head(
    const float* __restrict__ h, const int* __restrict__ batch,
    const float* __restrict__ Wfc, const float* __restrict__ bfc,
    float* __restrict__ out, int N)
{
    __shared__ float ssum[4][HID];
    __shared__ float scnt[4];
    __shared__ float smean[HID];
    __shared__ float slog[TYPE_NUM];

    int tid = threadIdx.x;
    int g = tid >> 6;
    int d = tid & 63;

    float acc = 0.f;
    int cnt = 0;
    for (int i = g; i < N; i += 4) {
        if (batch[i] != 0) break;
        acc += h[(size_t)i * HID + d];
        cnt++;
    }
    ssum[g][d] = acc;
    if (d == 0) scnt[g] = (float)cnt;
    __syncthreads();

    if (tid < HID) {
        float m = ssum[0][tid] + ssum[1][tid] + ssum[2][tid] + ssum[3][tid];
        float c = scnt[0] + scnt[1] + scnt[2] + scnt[3];
        smean[tid] = m / fmaxf(c, 1.f);
    }
    __syncthreads();

    if (tid < TYPE_NUM) {
        float l = bfc[tid];
        #pragma unroll
        for (int k = 0; k < HID; k++) l += smean[k] * Wfc[k * TYPE_NUM + tid];
        slog[tid] = l;
    }
    __syncthreads();

    if (tid == 0) {
        float mx = slog[0];
        #pragma unroll
        for (int j = 1; j < TYPE_NUM; j++) mx = fmaxf(mx, slog[j]);
        float s = 0.f;
        float ex[TYPE_NUM];
        #pragma unroll
        for (int j = 0; j < TYPE_NUM; j++) { ex[j] = __expf(slog[j] - mx); s += ex[j]; }
        float inv = 1.f / s;
        #pragma unroll
        for (int j = 0; j < TYPE_NUM; j++) out[j] = ex[j] * inv;
    }
}

// ---------------------------------------------------------------------------
extern "C" void kernel_launch(void* const* d_in, const int* in_sizes, int n_in,
                              void* d_out, int out_size)
{
    const float* x      = (const float*)d_in[0];
    const int*   ei     = (const int*)  d_in[1];
    const int*   batch  = (const int*)  d_in[2];
    const float* Wrel1  = (const float*)d_in[3];
    const float* Wroot1 = (const float*)d_in[4];
    const float* Wrel2  = (const float*)d_in[5];
    const float* Wroot2 = (const float*)d_in[6];
    const float* Wrel3  = (const float*)d_in[7];
    const float* Wroot3 = (const float*)d_in[8];
    const float* Wfc    = (const float*)d_in[9];
    const float* bfc    = (const float*)d_in[10];
    float* out = (float*)d_out;

    float4 *py4, *prA4, *prB4;
    unsigned char* pflag;
    int *pdeg, *prow, *pcur, *pcsr;
    cudaGetSymbolAddress((void**)&py4,   g_y);
    cudaGetSymbolAddress((void**)&prA4,  g_rA);
    cudaGetSymbolAddress((void**)&prB4,  g_rB);
    cudaGetSymbolAddress((void**)&pflag, g_flag);
    cudaGetSymbolAddress((void**)&pdeg,  g_deg);
    cudaGetSymbolAddress((void**)&prow,  g_rowptr);
    cudaGetSymbolAddress((void**)&pcur,  g_cursor);
    cudaGetSymbolAddress((void**)&pcsr,  g_csr);
    float* py  = (float*)py4;
    float* prA = (float*)prA4;
    float* prB = (float*)prB4;

    static cudaStream_t sSide = nullptr;
    static cudaEvent_t  evFork = nullptr, evJoin = nullptr;
    if (sSide == nullptr) {
        cudaStreamCreateWithFlags(&sSide, cudaStreamNonBlocking);
        cudaEventCreateWithFlags(&evFork, cudaEventDisableTiming);
        cudaEventCreateWithFlags(&evJoin, cudaEventDisableTiming);
        cudaFuncSetAttribute(dual_gemm<FEAT>,
                             cudaFuncAttributeMaxDynamicSharedMemorySize,
                             SMEM_GEMM1);
        cudaFuncSetAttribute(dual_gemm<HID>,
                             cudaFuncAttributeMaxDynamicSharedMemorySize,
                             SMEM_GEMM2);
    }

    const int N = N_NODES, E = N_EDGES;
    const int N4 = N / 4;
    const int nodeB = (N + 255) / 256;
    const int edgeB = (E + 255) / 256;
    const int gemmB = (N + 127) / 128;          // 128-row tiles
    const int gemm3B = (N + 63) / 64;           // gemm3 keeps 64-row tiles
    const int gathB = (N * 16 + 255) / 256;

    // ---- fork: CSR build on side stream, concurrent with gemm1 ----
    // Submission order keeps dual_gemm<FEAT> at launch slot #4 for ncu.
    cudaEventRecord(evFork, 0);
    cudaStreamWaitEvent(sSide, evFork, 0);
    node_init  <<<nodeB, 256, 0, sSide>>>(batch, pdeg, pflag, N);          // 1
    edge_hist  <<<edgeB, 256, 0, sSide>>>(ei, batch, pdeg, pflag, E);      // 2
    scan_rowptr<<<1, 1024, 0, sSide>>>((const int4*)pdeg, (int4*)prow,
                                       (int4*)pcur, N4);                   // 3
    dual_gemm<FEAT><<<gemmB, 256, SMEM_GEMM1>>>(x, Wrel1, Wroot1,
                                                py, prA, N);               // 4 (profiled)
    fill_csr   <<<edgeB, 256, 0, sSide>>>(ei, pcur, pcsr, E);              // 5
    cudaEventRecord(evJoin, sSide);
    cudaStreamWaitEvent(0, evJoin, 0);

    // Layer 1 aggregate: h1 = relu(gather(y1) + rA)
    gather_agg<0><<<gathB, 256>>>(py4, prow, pdeg, pcsr, pflag, prA4, N);  // 6

    // Layer 2: y2 = h1@Wrel2, rB = h1@Wroot2; h2 = relu(gather(y2)+rB) on flagged
    dual_gemm<HID><<<gemmB, 256, SMEM_GEMM2>>>(prA, Wrel2, Wroot2,
                                               py, prB, N);                // 7
    gather_agg<1><<<gathB, 256>>>(py4, prow, pdeg, pcsr, pflag, prB4, N);  // 8

    // Layer 3 fused gather+GEMM on graph-0 prefix
    gemm3_fused<<<gemm3B, 256>>>(prB4, prB, Wrel3, Wroot3,
                                 prow, pdeg, pcsr, batch, prA, N);         // 9

    // Head
    pool_head<<<1, 256>>>(prA, batch, Wfc, bfc, out, N);                   // 10
}

// round 17
// speedup vs baseline: 1.2052x; 1.0174x over previous
#include <cuda_runtime.h>
#include <cuda_bf16.h>
#include <math.h>

#define N_NODES 50000
#define N_EDGES 800000
#define FEAT    128
#define HID     64
#define TYPE_NUM 10

// ---------------- scratch buffers (float4-typed => 16B alignment) -----------
__device__ float4 g_y [N_NODES * HID / 4];   // transformed features
__device__ float4 g_rA[N_NODES * HID / 4];   // root part / h (ping)
__device__ float4 g_rB[N_NODES * HID / 4];   // root part / h (pong)
__device__ unsigned char g_flag[N_NODES];    // layer-2 active-node flags
__device__ int g_deg   [N_NODES];
__device__ int g_rowptr[N_NODES];
__device__ int g_cursor[N_NODES];
__device__ int g_csr   [N_EDGES];            // src node per CSR slot

// packed f32x2 helpers --------------------------------------------------------
#define FMA2(acc, a, b) \
    asm("fma.rn.f32x2 %0, %1, %2, %3;" : "=l"(acc) : "l"(a), "l"(b), "l"(acc))

__device__ __forceinline__ unsigned long long bcast2(float v) {
    unsigned long long r;
    unsigned u = __float_as_uint(v);
    asm("mov.b64 %0, {%1, %1};" : "=l"(r) : "r"(u));
    return r;
}
__device__ __forceinline__ float f2_lo(unsigned long long v) {
    return __uint_as_float((unsigned)v);
}
__device__ __forceinline__ float f2_hi(unsigned long long v) {
    return __uint_as_float((unsigned)(v >> 32));
}

// cp.async helpers ------------------------------------------------------------
__device__ __forceinline__ void cp4(void* dst, const void* src, int szbytes) {
    unsigned d = (unsigned)__cvta_generic_to_shared(dst);
    asm volatile("cp.async.ca.shared.global [%0], [%1], 4, %2;"
                 :: "r"(d), "l"(src), "r"(szbytes));
}
__device__ __forceinline__ void cp16(void* dst, const void* src) {
    unsigned d = (unsigned)__cvta_generic_to_shared(dst);
    asm volatile("cp.async.cg.shared.global [%0], [%1], 16;"
                 :: "r"(d), "l"(src));
}
#define CP_COMMIT() asm volatile("cp.async.commit_group;")
#define CP_WAIT0()  asm volatile("cp.async.wait_group 0;")

// ---------------------------------------------------------------------------
// CSR build
// ---------------------------------------------------------------------------
__global__ void __launch_bounds__(256) node_init(
    const int* __restrict__ batch, int* __restrict__ deg,
    unsigned char* __restrict__ flag, int N)
{
    int t = blockIdx.x * 256 + threadIdx.x;
    if (t >= N) return;
    deg[t] = 0;
    flag[t] = (batch[t] == 0) ? 1 : 0;
}

__global__ void __launch_bounds__(256) edge_hist(
    const int* __restrict__ ei, const int* __restrict__ batch,
    int* __restrict__ deg, unsigned char* __restrict__ flag, int E)
{
    int t = blockIdx.x * 256 + threadIdx.x;
    if (t >= E) return;
    int s = ei[t];
    int d = ei[E + t];
    atomicAdd(&deg[d], 1);
    if (batch[d] == 0) flag[s] = 1;
}

// Single-block exclusive scan, 4 elems/thread (int4): 13 chunks for N=50000.
__global__ void __launch_bounds__(1024) scan_rowptr(
    const int4* __restrict__ deg4, int4* __restrict__ rowptr4,
    int4* __restrict__ cursor4, int N4)
{
    __shared__ int warpsum[32];
    __shared__ int sBase;
    const int tid  = threadIdx.x;
    const int lane = tid & 31;
    const int wid  = tid >> 5;
    if (tid == 0) sBase = 0;
    __syncthreads();
    const int nchunk = (N4 + 1023) >> 10;
    for (int c = 0; c < nchunk; c++) {
        int idx = (c << 10) + tid;
        int4 v = (idx < N4) ? deg4[idx] : make_int4(0, 0, 0, 0);
        int s = v.x + v.y + v.z + v.w;
        int x = s;
        #pragma unroll
        for (int d = 1; d < 32; d <<= 1) {
            int t = __shfl_up_sync(0xffffffff, x, d);
            if (lane >= d) x += t;
        }
        if (lane == 31) warpsum[wid] = x;
        __syncthreads();
        if (wid == 0) {
            int w = warpsum[lane];
            #pragma unroll
            for (int d = 1; d < 32; d <<= 1) {
                int t = __shfl_up_sync(0xffffffff, w, d);
                if (lane >= d) w += t;
            }
            warpsum[lane] = w;
        }
        __syncthreads();
        int incl = x + (wid > 0 ? warpsum[wid - 1] : 0);
        int base = sBase;
        if (idx < N4) {
            int e0 = base + incl - s;
            int4 o;
            o.x = e0;
            o.y = e0 + v.x;
            o.z = o.y + v.y;
            o.w = o.z + v.z;
            rowptr4[idx] = o;
            cursor4[idx] = o;
        }
        __syncthreads();
        if (tid == 1023) sBase = base + incl;
        __syncthreads();
    }
}

__global__ void __launch_bounds__(256) fill_csr(
    const int* __restrict__ ei, int* __restrict__ cursor,
    int* __restrict__ csr, int E)
{
    int t = blockIdx.x * 256 + threadIdx.x;
    if (t >= E) return;
    int d = ei[E + t];
    int slot = atomicAdd(&cursor[d], 1);
    csr[slot] = ei[t];
}

// ---------------------------------------------------------------------------
// Dual GEMM, 64-row tiles, 4 rows x 4 contiguous cols x 2 mats per thread.
//  - weights (natural layout) loaded once per block via 16B cp.async
//  - input tile double-buffered via 4B cp.async (transposed smem)
//  - acc lo/hi = adjacent columns -> 8B stores
// Dynamic smem: 2*32*68 + 2*K*64 floats.
// ---------------------------------------------------------------------------
template<int K>
__global__ void __launch_bounds__(256, 2) dual_gemm(
    const float* __restrict__ in,
    const float* __restrict__ Wr,  const float* __restrict__ Wo,
    float* __restrict__ y, float* __restrict__ r, int N)
{
    extern __shared__ float smem[];
    float (*sIn)[32][68] = (float(*)[32][68])smem;           // [buf][k][row]
    float (*sWr)[64] = (float(*)[64])(smem + 2 * 32 * 68);   // [K][64] natural
    float (*sWo)[64] = (float(*)[64])(smem + 2 * 32 * 68 + K * 64);

    const int tid  = threadIdx.x;
    const int colq = tid & 15;          // cols colq*4 .. colq*4+3
    const int rowg = tid >> 4;          // rows rowg*4 .. rowg*4+3
    const int row0 = blockIdx.x * 64;

    // ---- prologue: all weights (16B cp.async) + input tile 0 ----
    #pragma unroll
    for (int e = 0; e < K / 16; e++) {
        int linear = tid + e * 256;     // float4 index, 0 .. K*16-1
        int kk = linear >> 4;
        int f4 = linear & 15;
        cp16(&sWr[kk][f4 * 4], &Wr[(size_t)kk * HID + f4 * 4]);
        cp16(&sWo[kk][f4 * 4], &Wo[(size_t)kk * HID + f4 * 4]);
    }
    #pragma unroll
    for (int e = 0; e < 8; e++) {
        int linear = tid + e * 256;
        int rl = linear >> 5;
        int kl = linear & 31;
        int grow = row0 + rl;
        cp4(&sIn[0][kl][rl], &in[(size_t)grow * K + kl], grow < N ? 4 : 0);
    }
    CP_COMMIT();

    unsigned long long accY[2][4], accR[2][4];   // [colpair][row]
    #pragma unroll
    for (int cp = 0; cp < 2; cp++)
        #pragma unroll
        for (int j = 0; j < 4; j++) { accY[cp][j] = 0ull; accR[cp][j] = 0ull; }

    int buf = 0;
    for (int kc = 0; kc < K; kc += 32) {
        CP_WAIT0();
        __syncthreads();
        if (kc + 32 < K) {
            #pragma unroll
            for (int e = 0; e < 8; e++) {
                int linear = tid + e * 256;
                int rl = linear >> 5;
                int kl = linear & 31;
                int grow = row0 + rl;
                cp4(&sIn[buf ^ 1][kl][rl],
                    &in[(size_t)grow * K + kc + 32 + kl], grow < N ? 4 : 0);
            }
            CP_COMMIT();
        }

        #pragma unroll
        for (int k = 0; k < 32; k++) {
            // wr.x = cols (4colq, 4colq+1), wr.y = cols (4colq+2, 4colq+3)
            ulonglong2 wr = *(const ulonglong2*)(&sWr[kc + k][colq * 4]);
            ulonglong2 wo = *(const ulonglong2*)(&sWo[kc + k][colq * 4]);
            float4 av = *(const float4*)(&sIn[buf][k][rowg * 4]);
            unsigned long long a0 = bcast2(av.x), a1 = bcast2(av.y);
            unsigned long long a2 = bcast2(av.z), a3 = bcast2(av.w);
            FMA2(accY[0][0], wr.x, a0);  FMA2(accY[1][0], wr.y, a0);
            FMA2(accY[0][1], wr.x, a1);  FMA2(accY[1][1], wr.y, a1);
            FMA2(accY[0][2], wr.x, a2);  FMA2(accY[1][2], wr.y, a2);
            FMA2(accY[0][3], wr.x, a3);  FMA2(accY[1][3], wr.y, a3);
            FMA2(accR[0][0], wo.x, a0);  FMA2(accR[1][0], wo.y, a0);
            FMA2(accR[0][1], wo.x, a1);  FMA2(accR[1][1], wo.y, a1);
            FMA2(accR[0][2], wo.x, a2);  FMA2(accR[1][2], wo.y, a2);
            FMA2(accR[0][3], wo.x, a3);  FMA2(accR[1][3], wo.y, a3);
        }
        buf ^= 1;
    }

    // acc[cp][j]: lo = col 4colq+2cp, hi = col 4colq+2cp+1 -> one 8B store
    const int rb = row0 + rowg * 4;
    #pragma unroll
    for (int j = 0; j < 4; j++) {
        int grow = rb + j;
        if (grow < N) {
            unsigned long long* yp =
                (unsigned long long*)(&y[(size_t)grow * HID + colq * 4]);
            unsigned long long* rp =
                (unsigned long long*)(&r[(size_t)grow * HID + colq * 4]);
            yp[0] = accY[0][j];
            yp[1] = accY[1][j];
            rp[0] = accR[0][j];
            rp[1] = accR[1][j];
        }
    }
}

static const int SMEM_GEMM1 = (2 * 32 * 68 + 2 * FEAT * 64) * 4;  // 82,944 B
static const int SMEM_GEMM2 = (2 * 32 * 68 + 2 * HID  * 64) * 4;  // 50,176 B

// ---------------------------------------------------------------------------
// CSR gather aggregation. 16 threads per node, register accumulation.
// MODE 0: all nodes,      out = relu(acc + r)   (in place over r)
// MODE 1: flagged nodes,  out = relu(acc + r)
// ---------------------------------------------------------------------------
template<int MODE>
__global__ void __launch_bounds__(256) gather_agg(
    const float4* __restrict__ y, const int* __restrict__ rowptr,
    const int* __restrict__ deg, const int* __restrict__ csr,
    const unsigned char* __restrict__ flag,
    float4* r_io, int N)
{
    int t = blockIdx.x * 256 + threadIdx.x;
    int node = t >> 4;
    if (node >= N) return;
    if (MODE == 1 && !flag[node]) return;
    int lane = t & 15;
    int start = rowptr[node];
    int end   = start + deg[node];

    float4 acc = make_float4(0.f, 0.f, 0.f, 0.f);
    int e = start;
    for (; e + 4 <= end; e += 4) {
        int s0 = csr[e], s1 = csr[e+1], s2 = csr[e+2], s3 = csr[e+3];
        float4 v0 = y[(size_t)s0 * 16 + lane];
        float4 v1 = y[(size_t)s1 * 16 + lane];
        float4 v2 = y[(size_t)s2 * 16 + lane];
        float4 v3 = y[(size_t)s3 * 16 + lane];
        acc.x += (v0.x + v1.x) + (v2.x + v3.x);
        acc.y += (v0.y + v1.y) + (v2.y + v3.y);
        acc.z += (v0.z + v1.z) + (v2.z + v3.z);
        acc.w += (v0.w + v1.w) + (v2.w + v3.w);
    }
    for (; e < end; e++) {
        float4 v = y[(size_t)csr[e] * 16 + lane];
        acc.x += v.x; acc.y += v.y; acc.z += v.z; acc.w += v.w;
    }

    size_t o = (size_t)node * 16 + lane;
    float4 b = r_io[o];
    b.x = fmaxf(acc.x + b.x, 0.f);
    b.y = fmaxf(acc.y + b.y, 0.f);
    b.z = fmaxf(acc.z + b.z, 0.f);
    b.w = fmaxf(acc.w + b.w, 0.f);
    r_io[o] = b;
}

// ---------------------------------------------------------------------------
// Layer 3 fused: graph-0 prefix tiles gather agg3 = sum h2[src] straight into
// smem, then h3 = relu(agg3@Wr + h2@Wo). Non-prefix tiles exit immediately.
// ---------------------------------------------------------------------------
__global__ void __launch_bounds__(256) gemm3_fused(
    const float4* __restrict__ h2_4, const float* __restrict__ h2,
    const float* __restrict__ Wr,  const float* __restrict__ Wo,
    const int* __restrict__ rowptr, const int* __restrict__ deg,
    const int* __restrict__ csr, const int* __restrict__ batch,
    float* __restrict__ h3, int N)
{
    const int row0 = blockIdx.x * 64;
    if (batch[row0] != 0) return;

    __shared__ float sA[64][68];    // gathered agg, [k][row], all K=64
    __shared__ float sB[32][68];    // h2 tile, [k][row]
    __shared__ float sWr[32][64];   // permuted
    __shared__ float sWo[32][64];   // permuted

    const int tid  = threadIdx.x;
    const int colq = tid & 15;
    const int rowg = tid >> 4;

    // ---- gather phase: 16 threads per node, 16 nodes per pass, 4 passes ----
    {
        int lane = tid & 15;
        int ng   = tid >> 4;
        #pragma unroll
        for (int pass = 0; pass < 4; pass++) {
            int row  = pass * 16 + ng;
            int grow = row0 + row;
            float4 acc = make_float4(0.f, 0.f, 0.f, 0.f);
            if (grow < N) {
                int start = rowptr[grow];
                int end   = start + deg[grow];
                for (int e = start; e < end; e++) {
                    float4 v = h2_4[(size_t)csr[e] * 16 + lane];
                    acc.x += v.x; acc.y += v.y; acc.z += v.z; acc.w += v.w;
                }
            }
            sA[lane * 4 + 0][row] = acc.x;
            sA[lane * 4 + 1][row] = acc.y;
            sA[lane * 4 + 2][row] = acc.z;
            sA[lane * 4 + 3][row] = acc.w;
        }
    }

    unsigned long long acc[2][4];
    #pragma unroll
    for (int cp = 0; cp < 2; cp++)
        #pragma unroll
        for (int j = 0; j < 4; j++) acc[cp][j] = 0ull;

    for (int kc = 0; kc < HID; kc += 32) {
        __syncthreads();
        #pragma unroll
        for (int e = 0; e < 8; e++) {
            int linear = tid + e * 256;
            int rl = linear >> 5;
            int kl = linear & 31;
            int grow = row0 + rl;
            sB[kl][rl] = (grow < N) ? h2[(size_t)grow * HID + kc + kl] : 0.f;
        }
        #pragma unroll
        for (int e = 0; e < 8; e++) {
            int linear = tid + e * 256;
            int kk = linear >> 6;
            int cc = linear & 63;
            int pos = (cc & 15) * 4 + (cc >> 4);
            sWr[kk][pos] = Wr[(size_t)(kc + kk) * HID + cc];
            sWo[kk][pos] = Wo[(size_t)(kc + kk) * HID + cc];
        }
        __syncthreads();

        #pragma unroll
        for (int k = 0; k < 32; k++) {
            ulonglong2 wr = *(const ulonglong2*)(&sWr[k][colq * 4]);
            ulonglong2 wo = *(const ulonglong2*)(&sWo[k][colq * 4]);
            float4 av = *(const float4*)(&sA[kc + k][rowg * 4]);
            float4 bv = *(const float4*)(&sB[k][rowg * 4]);
            unsigned long long a0 = bcast2(av.x), a1 = bcast2(av.y);
            unsigned long long a2 = bcast2(av.z), a3 = bcast2(av.w);
            unsigned long long b0 = bcast2(bv.x), b1 = bcast2(bv.y);
            unsigned long long b2 = bcast2(bv.z), b3 = bcast2(bv.w);
            FMA2(acc[0][0], wr.x, a0);  FMA2(acc[1][0], wr.y, a0);
            FMA2(acc[0][1], wr.x, a1);  FMA2(acc[1][1], wr.y, a1);
            FMA2(acc[0][2], wr.x, a2);  FMA2(acc[1][2], wr.y, a2);
            FMA2(acc[0][3], wr.x, a3);  FMA2(acc[1][3], wr.y, a3);
            FMA2(acc[0][0], wo.x, b0);  FMA2(acc[1][0], wo.y, b0);
            FMA2(acc[0][1], wo.x, b1);  FMA2(acc[1][1], wo.y, b1);
            FMA2(acc[0][2], wo.x, b2);  FMA2(acc[1][2], wo.y, b2);
            FMA2(acc[0][3], wo.x, b3);  FMA2(acc[1][3], wo.y, b3);
        }
    }

    const int rb = row0 + rowg * 4;
    #pragma unroll
    for (int cp = 0; cp < 2; cp++) {
        int cLo = colq + 32 * cp;
        int cHi = cLo + 16;
        #pragma unroll
        for (int j = 0; j < 4; j++) {
            int grow = rb + j;
            if (grow < N) {
                h3[(size_t)grow * HID + cLo] = fmaxf(f2_lo(acc[cp][j]), 0.f);
                h3[(size_t)grow * HID + cHi] = fmaxf(f2_hi(acc[cp][j]), 0.f);
            }
        }
    }
}

// ---------------------------------------------------------------------------
// Mean-pool graph 0, fc head, softmax
// ---------------------------------------------------------------------------
__global__ void __launch_bounds__(256) pool_head(
    const float* __restrict__ h, const int* __restrict__ batch,
    const float* __restrict__ Wfc, const float* __restrict__ bfc,
    float* __restrict__ out, int N)
{
    __shared__ float ssum[4][HID];
    __shared__ float scnt[4];
    __shared__ float smean[HID];
    __shared__ float slog[TYPE_NUM];

    int tid = threadIdx.x;
    int g = tid >> 6;
    int d = tid & 63;

    float acc = 0.f;
    int cnt = 0;
    for (int i = g; i < N; i += 4) {
        if (batch[i] != 0) break;
        acc += h[(size_t)i * HID + d];
        cnt++;
    }
    ssum[g][d] = acc;
    if (d == 0) scnt[g] = (float)cnt;
    __syncthreads();

    if (tid < HID) {
        float m = ssum[0][tid] + ssum[1][tid] + ssum[2][tid] + ssum[3][tid];
        float c = scnt[0] + scnt[1] + scnt[2] + scnt[3];
        smean[tid] = m / fmaxf(c, 1.f);
    }
    __syncthreads();

    if (tid < TYPE_NUM) {
        float l = bfc[tid];
        #pragma unroll
        for (int k = 0; k < HID; k++) l += smean[k] * Wfc[k * TYPE_NUM + tid];
        slog[tid] = l;
    }
    __syncthreads();

    if (tid == 0) {
        float mx = slog[0];
        #pragma unroll
        for (int j = 1; j < TYPE_NUM; j++) mx = fmaxf(mx, slog[j]);
        float s = 0.f;
        float ex[TYPE_NUM];
        #pragma unroll
        for (int j = 0; j < TYPE_NUM; j++) { ex[j] = __expf(slog[j] - mx); s += ex[j]; }
        float inv = 1.f / s;
        #pragma unroll
        for (int j = 0; j < TYPE_NUM; j++) out[j] = ex[j] * inv;
    }
}

// ---------------------------------------------------------------------------
extern "C" void kernel_launch(void* const* d_in, const int* in_sizes, int n_in,
                              void* d_out, int out_size)
{
    const float* x      = (const float*)d_in[0];
    const int*   ei     = (const int*)  d_in[1];
    const int*   batch  = (const int*)  d_in[2];
    const float* Wrel1  = (const float*)d_in[3];
    const float* Wroot1 = (const float*)d_in[4];
    const float* Wrel2  = (const float*)d_in[5];
    const float* Wroot2 = (const float*)d_in[6];
    const float* Wrel3  = (const float*)d_in[7];
    const float* Wroot3 = (const float*)d_in[8];
    const float* Wfc    = (const float*)d_in[9];
    const float* bfc    = (const float*)d_in[10];
    float* out = (float*)d_out;

    float4 *py4, *prA4, *prB4;
    unsigned char* pflag;
    int *pdeg, *prow, *pcur, *pcsr;
    cudaGetSymbolAddress((void**)&py4,   g_y);
    cudaGetSymbolAddress((void**)&prA4,  g_rA);
    cudaGetSymbolAddress((void**)&prB4,  g_rB);
    cudaGetSymbolAddress((void**)&pflag, g_flag);
    cudaGetSymbolAddress((void**)&pdeg,  g_deg);
    cudaGetSymbolAddress((void**)&prow,  g_rowptr);
    cudaGetSymbolAddress((void**)&pcur,  g_cursor);
    cudaGetSymbolAddress((void**)&pcsr,  g_csr);
    float* py  = (float*)py4;
    float* prA = (float*)prA4;
    float* prB = (float*)prB4;

    static cudaStream_t sSide = nullptr;
    static cudaEvent_t  evFork = nullptr, evJoin = nullptr;
    if (sSide == nullptr) {
        cudaStreamCreateWithFlags(&sSide, cudaStreamNonBlocking);
        cudaEventCreateWithFlags(&evFork, cudaEventDisableTiming);
        cudaEventCreateWithFlags(&evJoin, cudaEventDisableTiming);
        cudaFuncSetAttribute(dual_gemm<FEAT>,
                             cudaFuncAttributeMaxDynamicSharedMemorySize,
                             SMEM_GEMM1);
        cudaFuncSetAttribute(dual_gemm<HID>,
                             cudaFuncAttributeMaxDynamicSharedMemorySize,
                             SMEM_GEMM2);
    }

    const int N = N_NODES, E = N_EDGES;
    const int N4 = N / 4;
    const int nodeB = (N + 255) / 256;
    const int edgeB = (E + 255) / 256;
    const int gemmB = (N + 63) / 64;            // 64-row tiles
    const int gathB = (N * 16 + 255) / 256;

    // ---- fork: CSR build on side stream, concurrent with gemm1 ----
    // Submission order keeps dual_gemm<FEAT> at launch slot #4 for ncu.
    cudaEventRecord(evFork, 0);
    cudaStreamWaitEvent(sSide, evFork, 0);
    node_init  <<<nodeB, 256, 0, sSide>>>(batch, pdeg, pflag, N);          // 1
    edge_hist  <<<edgeB, 256, 0, sSide>>>(ei, batch, pdeg, pflag, E);      // 2
    scan_rowptr<<<1, 1024, 0, sSide>>>((const int4*)pdeg, (int4*)prow,
                                       (int4*)pcur, N4);                   // 3
    dual_gemm<FEAT><<<gemmB, 256, SMEM_GEMM1>>>(x, Wrel1, Wroot1,
                                                py, prA, N);               // 4 (profiled)
    fill_csr   <<<edgeB, 256, 0, sSide>>>(ei, pcur, pcsr, E);              // 5
    cudaEventRecord(evJoin, sSide);
    cudaStreamWaitEvent(0, evJoin, 0);

    // Layer 1 aggregate: h1 = relu(gather(y1) + rA)
    gather_agg<0><<<gathB, 256>>>(py4, prow, pdeg, pcsr, pflag, prA4, N);  // 6

    // Layer 2: y2 = h1@Wrel2, rB = h1@Wroot2; h2 = relu(gather(y2)+rB) on flagged
    dual_gemm<HID><<<gemmB, 256, SMEM_GEMM2>>>(prA, Wrel2, Wroot2,
                                               py, prB, N);                // 7
    gather_agg<1><<<gathB, 256>>>(py4, prow, pdeg, pcsr, pflag, prB4, N);  // 8

    // Layer 3 fused gather+GEMM on graph-0 prefix
    gemm3_fused<<<gemmB, 256>>>(prB4, prB, Wrel3, Wroot3,
                                prow, pdeg, pcsr, batch, prA, N);          // 9

    // Head
    pool_head<<<1, 256>>>(prA, batch, Wfc, bfc, out, N);                   // 10
}